// round 6
// baseline (speedup 1.0000x reference)
#include <cuda_runtime.h>

// Problem constants
#define Bv 4
#define Sv 2048
#define Dv 1024
#define Hv 16
#define HDv 64
#define N3v 3072
#define Mv (Bv*Sv)   // 8192

// ---------------- scratch (device globals; no runtime allocation) -------------
__device__ __align__(256) float g_q[Bv*Hv*Sv*HDv];   // (b,h,s,hd), q pre-scaled
__device__ __align__(256) float g_k[Bv*Hv*Sv*HDv];
__device__ __align__(256) float g_v[Bv*Hv*Sv*HDv];
__device__ __align__(256) float g_ctx[(size_t)Mv*Dv]; // attention output (b,s,d)

// ---------------- tf32 helpers ------------------------------------------------
__device__ __forceinline__ unsigned f2t(float f) {
    unsigned u;
    asm("cvt.rna.tf32.f32 %0, %1;" : "=r"(u) : "f"(f));
    return u;
}

__device__ __forceinline__ void mma8(float* c, const unsigned* a, const unsigned* b) {
    asm volatile(
        "mma.sync.aligned.m16n8k8.row.col.f32.tf32.tf32.f32 "
        "{%0,%1,%2,%3},{%4,%5,%6,%7},{%8,%9},{%0,%1,%2,%3};\n"
        : "+f"(c[0]), "+f"(c[1]), "+f"(c[2]), "+f"(c[3])
        : "r"(a[0]), "r"(a[1]), "r"(a[2]), "r"(a[3]),
          "r"(b[0]), "r"(b[1]));
}

// =============================================================================
// QKV scatter epilogue helper
// =============================================================================
__device__ __forceinline__ void qkv_store(int m, int n, float v, const float* __restrict__ bias) {
    v += bias[n];
    const int bb  = m >> 11;
    const int s   = m & 2047;
    const int sel = n >> 10;      // 0=q 1=k 2=v
    const int d   = n & 1023;
    const int h   = d >> 6;
    const int hd  = d & 63;
    const int idx = ((bb * Hv + h) * Sv + s) * HDv + hd;
    if (sel == 0)      g_q[idx] = v * 0.125f;
    else if (sel == 1) g_k[idx] = v;
    else               g_v[idx] = v;
}

// =============================================================================
// Kernel 1: QKV projection via tf32 mma.sync — C = X(8192x1024) @ W(1024x3072)+b
// 128x128 tile, BK=32, 256 threads (8 warps), warp tile 32x64.
// smem pitch 136: fragment loads bank = 8*t4 + g (+const) -> conflict-free.
// =============================================================================
#define GP 136

__global__ __launch_bounds__(256) void gemm_qkv_tc(
    const float* __restrict__ X,
    const float* __restrict__ W,
    const float* __restrict__ bias)
{
    __shared__ unsigned As[32 * GP];
    __shared__ unsigned Bs[32 * GP];

    const int t    = threadIdx.x;
    const int w    = t >> 5, lane = t & 31;
    const int g    = lane >> 2, tig = lane & 3;
    const int row0 = blockIdx.y * 128;
    const int col0 = blockIdx.x * 128;
    const int m0w  = (w & 3) * 32;
    const int n0w  = (w >> 2) * 64;

    const int ar  = t & 127;          // A row
    const int ah  = (t >> 7) * 16;    // A k-half
    const int bkr = t >> 3;           // B k-row
    const int bnc = (t & 7) * 16;     // B n-chunk

    float c[2][8][4];
    #pragma unroll
    for (int mt = 0; mt < 2; mt++)
        #pragma unroll
        for (int nt = 0; nt < 8; nt++)
            #pragma unroll
            for (int j = 0; j < 4; j++) c[mt][nt][j] = 0.f;

    for (int k0 = 0; k0 < Dv; k0 += 32) {
        // A tile -> As[k][m] (transposed, tf32)
        #pragma unroll
        for (int j = 0; j < 4; j++) {
            float4 v = *(const float4*)(X + (size_t)(row0 + ar) * Dv + k0 + ah + 4 * j);
            const int kb = ah + 4 * j;
            As[(kb + 0) * GP + ar] = f2t(v.x);
            As[(kb + 1) * GP + ar] = f2t(v.y);
            As[(kb + 2) * GP + ar] = f2t(v.z);
            As[(kb + 3) * GP + ar] = f2t(v.w);
        }
        // B tile -> Bs[k][n] (tf32)
        #pragma unroll
        for (int j = 0; j < 4; j++) {
            float4 v = *(const float4*)(W + (size_t)(k0 + bkr) * N3v + col0 + bnc + 4 * j);
            uint4 u = make_uint4(f2t(v.x), f2t(v.y), f2t(v.z), f2t(v.w));
            *(uint4*)(Bs + bkr * GP + bnc + 4 * j) = u;
        }
        __syncthreads();

        #pragma unroll
        for (int ks = 0; ks < 4; ks++) {
            const int kk = ks * 8;
            unsigned a[2][4], b[8][2];
            #pragma unroll
            for (int mt = 0; mt < 2; mt++) {
                const int mb = m0w + mt * 16;
                a[mt][0] = As[(kk + tig) * GP + mb + g];
                a[mt][1] = As[(kk + tig) * GP + mb + g + 8];
                a[mt][2] = As[(kk + tig + 4) * GP + mb + g];
                a[mt][3] = As[(kk + tig + 4) * GP + mb + g + 8];
            }
            #pragma unroll
            for (int nt = 0; nt < 8; nt++) {
                b[nt][0] = Bs[(kk + tig) * GP + n0w + nt * 8 + g];
                b[nt][1] = Bs[(kk + tig + 4) * GP + n0w + nt * 8 + g];
            }
            #pragma unroll
            for (int mt = 0; mt < 2; mt++)
                #pragma unroll
                for (int nt = 0; nt < 8; nt++)
                    mma8(c[mt][nt], a[mt], b[nt]);
        }
        __syncthreads();
    }

    // epilogue: scatter to q/k/v
    #pragma unroll
    for (int mt = 0; mt < 2; mt++) {
        const int r0 = row0 + m0w + mt * 16 + g;
        const int r1 = r0 + 8;
        #pragma unroll
        for (int nt = 0; nt < 8; nt++) {
            const int n = col0 + n0w + nt * 8 + 2 * tig;
            qkv_store(r0, n,     c[mt][nt][0], bias);
            qkv_store(r0, n + 1, c[mt][nt][1], bias);
            qkv_store(r1, n,     c[mt][nt][2], bias);
            qkv_store(r1, n + 1, c[mt][nt][3], bias);
        }
    }
}

// =============================================================================
// Kernel 3: out projection via tf32 mma.sync — out = ctx @ Wo(1024x1024) + b
// =============================================================================
__global__ __launch_bounds__(256) void gemm_out_tc(
    const float* __restrict__ W,
    const float* __restrict__ bias,
    float* __restrict__ out)
{
    __shared__ unsigned As[32 * GP];
    __shared__ unsigned Bs[32 * GP];

    const int t    = threadIdx.x;
    const int w    = t >> 5, lane = t & 31;
    const int g    = lane >> 2, tig = lane & 3;
    const int row0 = blockIdx.y * 128;
    const int col0 = blockIdx.x * 128;
    const int m0w  = (w & 3) * 32;
    const int n0w  = (w >> 2) * 64;

    const int ar  = t & 127;
    const int ah  = (t >> 7) * 16;
    const int bkr = t >> 3;
    const int bnc = (t & 7) * 16;

    float c[2][8][4];
    #pragma unroll
    for (int mt = 0; mt < 2; mt++)
        #pragma unroll
        for (int nt = 0; nt < 8; nt++)
            #pragma unroll
            for (int j = 0; j < 4; j++) c[mt][nt][j] = 0.f;

    for (int k0 = 0; k0 < Dv; k0 += 32) {
        #pragma unroll
        for (int j = 0; j < 4; j++) {
            float4 v = *(const float4*)(g_ctx + (size_t)(row0 + ar) * Dv + k0 + ah + 4 * j);
            const int kb = ah + 4 * j;
            As[(kb + 0) * GP + ar] = f2t(v.x);
            As[(kb + 1) * GP + ar] = f2t(v.y);
            As[(kb + 2) * GP + ar] = f2t(v.z);
            As[(kb + 3) * GP + ar] = f2t(v.w);
        }
        #pragma unroll
        for (int j = 0; j < 4; j++) {
            float4 v = *(const float4*)(W + (size_t)(k0 + bkr) * Dv + col0 + bnc + 4 * j);
            uint4 u = make_uint4(f2t(v.x), f2t(v.y), f2t(v.z), f2t(v.w));
            *(uint4*)(Bs + bkr * GP + bnc + 4 * j) = u;
        }
        __syncthreads();

        #pragma unroll
        for (int ks = 0; ks < 4; ks++) {
            const int kk = ks * 8;
            unsigned a[2][4], b[8][2];
            #pragma unroll
            for (int mt = 0; mt < 2; mt++) {
                const int mb = m0w + mt * 16;
                a[mt][0] = As[(kk + tig) * GP + mb + g];
                a[mt][1] = As[(kk + tig) * GP + mb + g + 8];
                a[mt][2] = As[(kk + tig + 4) * GP + mb + g];
                a[mt][3] = As[(kk + tig + 4) * GP + mb + g + 8];
            }
            #pragma unroll
            for (int nt = 0; nt < 8; nt++) {
                b[nt][0] = Bs[(kk + tig) * GP + n0w + nt * 8 + g];
                b[nt][1] = Bs[(kk + tig + 4) * GP + n0w + nt * 8 + g];
            }
            #pragma unroll
            for (int mt = 0; mt < 2; mt++)
                #pragma unroll
                for (int nt = 0; nt < 8; nt++)
                    mma8(c[mt][nt], a[mt], b[nt]);
        }
        __syncthreads();
    }

    #pragma unroll
    for (int mt = 0; mt < 2; mt++) {
        const int r0 = row0 + m0w + mt * 16 + g;
        const int r1 = r0 + 8;
        #pragma unroll
        for (int nt = 0; nt < 8; nt++) {
            const int n = col0 + n0w + nt * 8 + 2 * tig;
            float2 v0 = make_float2(c[mt][nt][0] + bias[n], c[mt][nt][1] + bias[n + 1]);
            float2 v1 = make_float2(c[mt][nt][2] + bias[n], c[mt][nt][3] + bias[n + 1]);
            *(float2*)(out + (size_t)r0 * Dv + n) = v0;
            *(float2*)(out + (size_t)r1 * Dv + n) = v1;
        }
    }
}

// =============================================================================
// Kernel 2: tf32 tensor-core flash attention.
// Block = 128 threads (4 warps); each warp owns 16 q-rows x ALL 64 keys,
// so softmax is entirely register+shuffle resident. P (C-frag) -> A-frag via
// intra-quad shuffles. sK pitch 68 / sV pitch 72: conflict-free B-frag loads.
// =============================================================================
#define PK 68
#define PV 72

__global__ __launch_bounds__(128) void attn_tc(const int* __restrict__ mask)
{
    __shared__ unsigned sK[64 * PK];
    __shared__ unsigned sV[64 * PV];
    __shared__ int smask[64];

    const int t    = threadIdx.x;
    const int w    = t >> 5, lane = t & 31;
    const int g    = lane >> 2, tig = lane & 3;
    const int qt   = blockIdx.x;
    const int h    = blockIdx.y;
    const int b    = blockIdx.z;
    const size_t bh = ((size_t)b * Hv + h) * Sv;

    // ---- preload Q fragments (rows w*16 .. w*16+15), tf32 ----
    unsigned q[8][4];
    const float* qp = g_q + (bh + qt * 64 + w * 16) * HDv;
    #pragma unroll
    for (int ks = 0; ks < 8; ks++) {
        q[ks][0] = f2t(qp[g * 64       + ks * 8 + tig]);
        q[ks][1] = f2t(qp[(g + 8) * 64 + ks * 8 + tig]);
        q[ks][2] = f2t(qp[g * 64       + ks * 8 + tig + 4]);
        q[ks][3] = f2t(qp[(g + 8) * 64 + ks * 8 + tig + 4]);
    }

    float o[8][4];
    #pragma unroll
    for (int nt = 0; nt < 8; nt++)
        #pragma unroll
        for (int j = 0; j < 4; j++) o[nt][j] = 0.f;

    float m0r = -1e30f, m1r = -1e30f, l0 = 0.f, l1 = 0.f;

    const int lr = t >> 1;            // 0..63 tile-load row
    const int lh = (t & 1) * 32;      // col half
    const int sub = tig & 1;
    const int sl0 = (lane & ~3) | (tig >> 1);
    const int sl2 = sl0 + 2;

    for (int kt = 0; kt < Sv / 64; kt++) {
        __syncthreads();   // protect prior-iteration smem reads

        // ---- load K/V tiles as tf32 ----
        const float* kp = g_k + (bh + kt * 64) * HDv;
        const float* vp = g_v + (bh + kt * 64) * HDv;
        #pragma unroll
        for (int j = 0; j < 8; j++) {
            float4 kv = *(const float4*)(kp + lr * 64 + lh + 4 * j);
            *(uint4*)(sK + lr * PK + lh + 4 * j) =
                make_uint4(f2t(kv.x), f2t(kv.y), f2t(kv.z), f2t(kv.w));
            float4 vv = *(const float4*)(vp + lr * 64 + lh + 4 * j);
            *(uint4*)(sV + lr * PV + lh + 4 * j) =
                make_uint4(f2t(vv.x), f2t(vv.y), f2t(vv.z), f2t(vv.w));
        }
        if (t < 64) smask[t] = mask[b * Sv + kt * 64 + t];
        __syncthreads();

        // ---- S = Q K^T ----
        float s[8][4];
        #pragma unroll
        for (int nt = 0; nt < 8; nt++)
            #pragma unroll
            for (int j = 0; j < 4; j++) s[nt][j] = 0.f;

        #pragma unroll
        for (int ks = 0; ks < 8; ks++) {
            const int kk = ks * 8;
            #pragma unroll
            for (int nt = 0; nt < 8; nt++) {
                unsigned bb[2];
                bb[0] = sK[(nt * 8 + g) * PK + kk + tig];
                bb[1] = sK[(nt * 8 + g) * PK + kk + tig + 4];
                mma8(s[nt], q[ks], bb);
            }
        }

        // ---- mask ----
        #pragma unroll
        for (int nt = 0; nt < 8; nt++) {
            const int cc = nt * 8 + 2 * tig;
            if (!smask[cc])     { s[nt][0] = -1e30f; s[nt][2] = -1e30f; }
            if (!smask[cc + 1]) { s[nt][1] = -1e30f; s[nt][3] = -1e30f; }
        }

        // ---- row max (regs + quad shuffle) ----
        float mx0 = -1e30f, mx1 = -1e30f;
        #pragma unroll
        for (int nt = 0; nt < 8; nt++) {
            mx0 = fmaxf(mx0, fmaxf(s[nt][0], s[nt][1]));
            mx1 = fmaxf(mx1, fmaxf(s[nt][2], s[nt][3]));
        }
        mx0 = fmaxf(mx0, __shfl_xor_sync(0xffffffffu, mx0, 1));
        mx0 = fmaxf(mx0, __shfl_xor_sync(0xffffffffu, mx0, 2));
        mx1 = fmaxf(mx1, __shfl_xor_sync(0xffffffffu, mx1, 1));
        mx1 = fmaxf(mx1, __shfl_xor_sync(0xffffffffu, mx1, 2));

        const float mn0 = fmaxf(m0r, mx0);
        const float mn1 = fmaxf(m1r, mx1);
        const float cr0 = __expf(m0r - mn0);
        const float cr1 = __expf(m1r - mn1);
        m0r = mn0; m1r = mn1;

        // ---- exp + row sums ----
        float a0 = 0.f, a1 = 0.f;
        #pragma unroll
        for (int nt = 0; nt < 8; nt++) {
            s[nt][0] = __expf(s[nt][0] - mn0);
            s[nt][1] = __expf(s[nt][1] - mn0);
            s[nt][2] = __expf(s[nt][2] - mn1);
            s[nt][3] = __expf(s[nt][3] - mn1);
            a0 += s[nt][0] + s[nt][1];
            a1 += s[nt][2] + s[nt][3];
        }
        a0 += __shfl_xor_sync(0xffffffffu, a0, 1);
        a0 += __shfl_xor_sync(0xffffffffu, a0, 2);
        a1 += __shfl_xor_sync(0xffffffffu, a1, 1);
        a1 += __shfl_xor_sync(0xffffffffu, a1, 2);
        l0 = l0 * cr0 + a0;
        l1 = l1 * cr1 + a1;

        // ---- rescale O ----
        #pragma unroll
        for (int nt = 0; nt < 8; nt++) {
            o[nt][0] *= cr0; o[nt][1] *= cr0;
            o[nt][2] *= cr1; o[nt][3] *= cr1;
        }

        // ---- P -> tf32 (in place) ----
        #pragma unroll
        for (int nt = 0; nt < 8; nt++)
            #pragma unroll
            for (int j = 0; j < 4; j++)
                s[nt][j] = __uint_as_float(f2t(s[nt][j]));

        // ---- O += P V  (C-frag -> A-frag via quad shuffles) ----
        #pragma unroll
        for (int ks = 0; ks < 8; ks++) {
            unsigned a[4];
            float p0 = __shfl_sync(0xffffffffu, s[ks][0], sl0);
            float p1 = __shfl_sync(0xffffffffu, s[ks][1], sl0);
            a[0] = __float_as_uint(sub ? p1 : p0);
            float p2 = __shfl_sync(0xffffffffu, s[ks][2], sl0);
            float p3 = __shfl_sync(0xffffffffu, s[ks][3], sl0);
            a[1] = __float_as_uint(sub ? p3 : p2);
            float r0 = __shfl_sync(0xffffffffu, s[ks][0], sl2);
            float r1 = __shfl_sync(0xffffffffu, s[ks][1], sl2);
            a[2] = __float_as_uint(sub ? r1 : r0);
            float r2 = __shfl_sync(0xffffffffu, s[ks][2], sl2);
            float r3 = __shfl_sync(0xffffffffu, s[ks][3], sl2);
            a[3] = __float_as_uint(sub ? r3 : r2);

            const int kk = ks * 8;
            #pragma unroll
            for (int nt = 0; nt < 8; nt++) {
                unsigned bb[2];
                bb[0] = sV[(kk + tig) * PV + nt * 8 + g];
                bb[1] = sV[(kk + tig + 4) * PV + nt * 8 + g];
                mma8(o[nt], a, bb);
            }
        }
    }

    // ---- normalize and write context (b, s, d) ----
    const float inv0 = 1.0f / l0;
    const float inv1 = 1.0f / l1;
    float* op = g_ctx + (size_t)(b * Sv + qt * 64 + w * 16) * Dv + h * HDv;
    #pragma unroll
    for (int nt = 0; nt < 8; nt++) {
        const int cc = nt * 8 + 2 * tig;
        *(float2*)(op + (size_t)g * Dv + cc) =
            make_float2(o[nt][0] * inv0, o[nt][1] * inv0);
        *(float2*)(op + (size_t)(g + 8) * Dv + cc) =
            make_float2(o[nt][2] * inv1, o[nt][3] * inv1);
    }
}

// =============================================================================
extern "C" void kernel_launch(void* const* d_in, const int* in_sizes, int n_in,
                              void* d_out, int out_size)
{
    const float* x     = (const float*)d_in[0];
    const float* w_in  = (const float*)d_in[1];
    const float* b_in  = (const float*)d_in[2];
    const float* w_out = (const float*)d_in[3];
    const float* b_out = (const float*)d_in[4];
    const int*   mask  = (const int*)d_in[5];
    float* out = (float*)d_out;

    gemm_qkv_tc<<<dim3(N3v / 128, Mv / 128), 256>>>(x, w_in, b_in);
    attn_tc<<<dim3(Sv / 64, Hv, Bv), 128>>>(mask);
    gemm_out_tc<<<dim3(Dv / 128, Mv / 128), 256>>>(w_out, b_out, out);
}

// round 7
// speedup vs baseline: 1.7297x; 1.7297x over previous
#include <cuda_runtime.h>

// Problem constants
#define Bv 4
#define Sv 2048
#define Dv 1024
#define Hv 16
#define HDv 64
#define N3v 3072
#define Mv (Bv*Sv)   // 8192

// ---------------- scratch (device globals; no runtime allocation) -------------
__device__ __align__(256) float g_q[Bv*Hv*Sv*HDv];   // (b,h,s,hd), q pre-scaled
__device__ __align__(256) float g_k[Bv*Hv*Sv*HDv];
__device__ __align__(256) float g_v[Bv*Hv*Sv*HDv];
__device__ __align__(256) float g_ctx[(size_t)Mv*Dv]; // attention output (b,s,d)

// ---------------- tf32 helpers ------------------------------------------------
__device__ __forceinline__ unsigned f2t(float f) {
    unsigned u;
    asm("cvt.rna.tf32.f32 %0, %1;" : "=r"(u) : "f"(f));
    return u;
}

__device__ __forceinline__ void mma8(float* c, const unsigned* a, const unsigned* b) {
    asm volatile(
        "mma.sync.aligned.m16n8k8.row.col.f32.tf32.tf32.f32 "
        "{%0,%1,%2,%3},{%4,%5,%6,%7},{%8,%9},{%0,%1,%2,%3};\n"
        : "+f"(c[0]), "+f"(c[1]), "+f"(c[2]), "+f"(c[3])
        : "r"(a[0]), "r"(a[1]), "r"(a[2]), "r"(a[3]),
          "r"(b[0]), "r"(b[1]));
}

// =============================================================================
// QKV scatter epilogue helper
// =============================================================================
__device__ __forceinline__ void qkv_store(int m, int n, float v, const float* __restrict__ bias) {
    v += bias[n];
    const int bb  = m >> 11;
    const int s   = m & 2047;
    const int sel = n >> 10;      // 0=q 1=k 2=v
    const int d   = n & 1023;
    const int h   = d >> 6;
    const int hd  = d & 63;
    const int idx = ((bb * Hv + h) * Sv + s) * HDv + hd;
    if (sel == 0)      g_q[idx] = v * 0.125f;
    else if (sel == 1) g_k[idx] = v;
    else               g_v[idx] = v;
}

// =============================================================================
// Unified tf32 GEMM: C(8192 x LDN) = A(8192x1024) @ W(1024xLDN) + bias
// 128x128 tile, BK=32, 256 threads (8 warps), warp tile 32x64.
// Paired-k smem layout: uint2 = (k, k+4) at pitch 132 (== 4 mod 16, so LDS.64
// fragment loads are bank-conflict-free). Register prefetch of next gmem tile
// overlaps global latency with the MMA loop.
// EPI 0: scatter into q/k/v.  EPI 1: plain store + bias to `out`.
// =============================================================================
#define GPP 132

template<int LDN, int EPI>
__global__ __launch_bounds__(256) void gemm_tc(
    const float* __restrict__ A,
    const float* __restrict__ W,
    const float* __restrict__ bias,
    float* __restrict__ out)
{
    __shared__ uint2 Ap[16 * GPP];
    __shared__ uint2 Bp[16 * GPP];

    const int t    = threadIdx.x;
    const int w    = t >> 5, lane = t & 31;
    const int g    = lane >> 2, tig = lane & 3;
    const int row0 = blockIdx.y * 128;
    const int col0 = blockIdx.x * 128;
    const int m0w  = (w & 3) * 32;
    const int n0w  = (w >> 2) * 64;

    const float* Aeff = (EPI == 0) ? A : g_ctx;

    // A loader: thread -> row ar, 16 consecutive k at ah
    const int ar = t & 127;
    const int ah = (t >> 7) * 16;
    // B loader: thread -> rows (bks*8+btig, +4), 8 cols at bn
    const int btig = t & 3;
    const int bnsel = (t >> 2) & 3;
    const int bks  = (t >> 4) & 3;
    const int bngrp = t >> 6;
    const int bn   = bngrp * 32 + bnsel * 8;
    const int br0  = bks * 8 + btig;

    float c[2][8][4];
    #pragma unroll
    for (int mt = 0; mt < 2; mt++)
        #pragma unroll
        for (int nt = 0; nt < 8; nt++)
            #pragma unroll
            for (int j = 0; j < 4; j++) c[mt][nt][j] = 0.f;

    float4 av[4], bv[4];

    auto loadG = [&](int k0) {
        const float* ap = Aeff + (size_t)(row0 + ar) * Dv + k0 + ah;
        av[0] = *(const float4*)(ap);
        av[1] = *(const float4*)(ap + 4);
        av[2] = *(const float4*)(ap + 8);
        av[3] = *(const float4*)(ap + 12);
        const float* bp0 = W + (size_t)(k0 + br0) * LDN + col0 + bn;
        const float* bp1 = bp0 + (size_t)4 * LDN;
        bv[0] = *(const float4*)(bp0);
        bv[1] = *(const float4*)(bp0 + 4);
        bv[2] = *(const float4*)(bp1);
        bv[3] = *(const float4*)(bp1 + 4);
    };
    auto storeS = [&]() {
        const float* aa = (const float*)av;
        const int ksb = ah >> 3;
        #pragma unroll
        for (int ksl = 0; ksl < 2; ksl++)
            #pragma unroll
            for (int tg = 0; tg < 4; tg++)
                Ap[((ksb + ksl) * 4 + tg) * GPP + ar] =
                    make_uint2(f2t(aa[ksl * 8 + tg]), f2t(aa[ksl * 8 + tg + 4]));
        const float* blo = (const float*)&bv[0];
        const float* bhi = (const float*)&bv[2];
        #pragma unroll
        for (int cc = 0; cc < 8; cc++)
            Bp[(bks * 4 + btig) * GPP + bn + cc] =
                make_uint2(f2t(blo[cc]), f2t(bhi[cc]));
    };

    loadG(0);
    storeS();
    __syncthreads();

    for (int k0 = 0; k0 < Dv; k0 += 32) {
        const bool last = (k0 + 32 >= Dv);
        if (!last) loadG(k0 + 32);

        #pragma unroll
        for (int ks = 0; ks < 4; ks++) {
            unsigned a[2][4];
            #pragma unroll
            for (int mt = 0; mt < 2; mt++) {
                uint2 p0 = Ap[(ks * 4 + tig) * GPP + m0w + mt * 16 + g];
                uint2 p1 = Ap[(ks * 4 + tig) * GPP + m0w + mt * 16 + g + 8];
                a[mt][0] = p0.x; a[mt][1] = p1.x; a[mt][2] = p0.y; a[mt][3] = p1.y;
            }
            #pragma unroll
            for (int nt = 0; nt < 8; nt++) {
                uint2 bp = Bp[(ks * 4 + tig) * GPP + n0w + nt * 8 + g];
                unsigned bb[2] = { bp.x, bp.y };
                mma8(c[0][nt], a[0], bb);
                mma8(c[1][nt], a[1], bb);
            }
        }
        __syncthreads();
        if (!last) { storeS(); __syncthreads(); }
    }

    if (EPI == 0) {
        #pragma unroll
        for (int mt = 0; mt < 2; mt++) {
            const int r0 = row0 + m0w + mt * 16 + g;
            const int r1 = r0 + 8;
            #pragma unroll
            for (int nt = 0; nt < 8; nt++) {
                const int n = col0 + n0w + nt * 8 + 2 * tig;
                qkv_store(r0, n,     c[mt][nt][0], bias);
                qkv_store(r0, n + 1, c[mt][nt][1], bias);
                qkv_store(r1, n,     c[mt][nt][2], bias);
                qkv_store(r1, n + 1, c[mt][nt][3], bias);
            }
        }
    } else {
        #pragma unroll
        for (int mt = 0; mt < 2; mt++) {
            const int r0 = row0 + m0w + mt * 16 + g;
            const int r1 = r0 + 8;
            #pragma unroll
            for (int nt = 0; nt < 8; nt++) {
                const int n = col0 + n0w + nt * 8 + 2 * tig;
                *(float2*)(out + (size_t)r0 * Dv + n) =
                    make_float2(c[mt][nt][0] + bias[n], c[mt][nt][1] + bias[n + 1]);
                *(float2*)(out + (size_t)r1 * Dv + n) =
                    make_float2(c[mt][nt][2] + bias[n], c[mt][nt][3] + bias[n + 1]);
            }
        }
    }
}

// =============================================================================
// tf32 tensor-core flash attention, q-tile 128, 256 threads (8 warps).
// Each warp owns 16 q-rows x ALL 64 keys -> softmax fully register/shuffle
// resident. K/V smem in paired-k uint2 layout (LDS.64, conflict-free pitches
// 36 / 68). P (C-frag) -> A-frag via intra-quad shuffles.
// =============================================================================
#define PKP 36
#define PVP 68

__global__ __launch_bounds__(256) void attn_tc(const int* __restrict__ mask)
{
    __shared__ uint2 sKp[64 * PKP];   // [key][hd-pair]   18432 B
    __shared__ uint2 sVp[32 * PVP];   // [key-pair][hd]   17408 B
    __shared__ int smask[64];

    const int t    = threadIdx.x;
    const int w    = t >> 5, lane = t & 31;
    const int g    = lane >> 2, tig = lane & 3;
    const int qt   = blockIdx.x;
    const int h    = blockIdx.y;
    const int b    = blockIdx.z;
    const size_t bh = ((size_t)b * Hv + h) * Sv;

    // ---- preload Q fragments (rows qt*128 + w*16 .. +15), tf32 ----
    unsigned q[8][4];
    const float* qp = g_q + (bh + qt * 128 + w * 16) * HDv;
    #pragma unroll
    for (int ks = 0; ks < 8; ks++) {
        q[ks][0] = f2t(qp[g * 64       + ks * 8 + tig]);
        q[ks][1] = f2t(qp[(g + 8) * 64 + ks * 8 + tig]);
        q[ks][2] = f2t(qp[g * 64       + ks * 8 + tig + 4]);
        q[ks][3] = f2t(qp[(g + 8) * 64 + ks * 8 + tig + 4]);
    }

    float o[8][4];
    #pragma unroll
    for (int nt = 0; nt < 8; nt++)
        #pragma unroll
        for (int j = 0; j < 4; j++) o[nt][j] = 0.f;

    float m0r = -1e30f, m1r = -1e30f, l0 = 0.f, l1 = 0.f;

    // K loader: row kr (0..63), 16 hd at kh0
    const int kr  = t >> 2;
    const int kh0 = (t & 3) * 16;
    // V loader: rows (vks*8+vtig, +4), 8 hd at vhd0   (vks == warp id)
    const int vtig = t & 3;
    const int vhd0 = ((t >> 2) & 7) * 8;
    const int vks  = t >> 5;
    const int vr0  = vks * 8 + vtig;

    const int sub = tig & 1;
    const int sl0 = (lane & ~3) | (tig >> 1);
    const int sl2 = sl0 + 2;

    for (int kt = 0; kt < Sv / 64; kt++) {
        __syncthreads();   // protect prior-iteration smem reads

        const float* kp = g_k + (bh + kt * 64) * HDv;
        const float* vp = g_v + (bh + kt * 64) * HDv;

        // ---- K tile: pairs over hd ----
        {
            float4 kv[4];
            #pragma unroll
            for (int j = 0; j < 4; j++)
                kv[j] = *(const float4*)(kp + kr * 64 + kh0 + 4 * j);
            const float* ka = (const float*)kv;
            const int ksb = kh0 >> 3;
            #pragma unroll
            for (int ksl = 0; ksl < 2; ksl++)
                #pragma unroll
                for (int tg = 0; tg < 4; tg++)
                    sKp[kr * PKP + (ksb + ksl) * 4 + tg] =
                        make_uint2(f2t(ka[ksl * 8 + tg]), f2t(ka[ksl * 8 + tg + 4]));
        }
        // ---- V tile: pairs over key ----
        {
            float4 v0a = *(const float4*)(vp + vr0 * 64 + vhd0);
            float4 v0b = *(const float4*)(vp + vr0 * 64 + vhd0 + 4);
            float4 v1a = *(const float4*)(vp + (vr0 + 4) * 64 + vhd0);
            float4 v1b = *(const float4*)(vp + (vr0 + 4) * 64 + vhd0 + 4);
            float vl[8] = { v0a.x, v0a.y, v0a.z, v0a.w, v0b.x, v0b.y, v0b.z, v0b.w };
            float vh[8] = { v1a.x, v1a.y, v1a.z, v1a.w, v1b.x, v1b.y, v1b.z, v1b.w };
            #pragma unroll
            for (int cc = 0; cc < 8; cc++)
                sVp[(vks * 4 + vtig) * PVP + vhd0 + cc] =
                    make_uint2(f2t(vl[cc]), f2t(vh[cc]));
        }
        if (t < 64) smask[t] = mask[b * Sv + kt * 64 + t];
        __syncthreads();

        // ---- S = Q K^T ----
        float s[8][4];
        #pragma unroll
        for (int nt = 0; nt < 8; nt++)
            #pragma unroll
            for (int j = 0; j < 4; j++) s[nt][j] = 0.f;

        #pragma unroll
        for (int ks = 0; ks < 8; ks++) {
            #pragma unroll
            for (int nt = 0; nt < 8; nt++) {
                uint2 bp = sKp[(nt * 8 + g) * PKP + ks * 4 + tig];
                unsigned bb[2] = { bp.x, bp.y };
                mma8(s[nt], q[ks], bb);
            }
        }

        // ---- mask ----
        #pragma unroll
        for (int nt = 0; nt < 8; nt++) {
            const int cc = nt * 8 + 2 * tig;
            if (!smask[cc])     { s[nt][0] = -1e30f; s[nt][2] = -1e30f; }
            if (!smask[cc + 1]) { s[nt][1] = -1e30f; s[nt][3] = -1e30f; }
        }

        // ---- row max (regs + quad shuffle) ----
        float mx0 = -1e30f, mx1 = -1e30f;
        #pragma unroll
        for (int nt = 0; nt < 8; nt++) {
            mx0 = fmaxf(mx0, fmaxf(s[nt][0], s[nt][1]));
            mx1 = fmaxf(mx1, fmaxf(s[nt][2], s[nt][3]));
        }
        mx0 = fmaxf(mx0, __shfl_xor_sync(0xffffffffu, mx0, 1));
        mx0 = fmaxf(mx0, __shfl_xor_sync(0xffffffffu, mx0, 2));
        mx1 = fmaxf(mx1, __shfl_xor_sync(0xffffffffu, mx1, 1));
        mx1 = fmaxf(mx1, __shfl_xor_sync(0xffffffffu, mx1, 2));

        const float mn0 = fmaxf(m0r, mx0);
        const float mn1 = fmaxf(m1r, mx1);
        const float cr0 = __expf(m0r - mn0);
        const float cr1 = __expf(m1r - mn1);
        m0r = mn0; m1r = mn1;

        // ---- exp + row sums ----
        float a0 = 0.f, a1 = 0.f;
        #pragma unroll
        for (int nt = 0; nt < 8; nt++) {
            s[nt][0] = __expf(s[nt][0] - mn0);
            s[nt][1] = __expf(s[nt][1] - mn0);
            s[nt][2] = __expf(s[nt][2] - mn1);
            s[nt][3] = __expf(s[nt][3] - mn1);
            a0 += s[nt][0] + s[nt][1];
            a1 += s[nt][2] + s[nt][3];
        }
        a0 += __shfl_xor_sync(0xffffffffu, a0, 1);
        a0 += __shfl_xor_sync(0xffffffffu, a0, 2);
        a1 += __shfl_xor_sync(0xffffffffu, a1, 1);
        a1 += __shfl_xor_sync(0xffffffffu, a1, 2);
        l0 = l0 * cr0 + a0;
        l1 = l1 * cr1 + a1;

        // ---- rescale O ----
        #pragma unroll
        for (int nt = 0; nt < 8; nt++) {
            o[nt][0] *= cr0; o[nt][1] *= cr0;
            o[nt][2] *= cr1; o[nt][3] *= cr1;
        }

        // ---- P -> tf32 (in place) ----
        #pragma unroll
        for (int nt = 0; nt < 8; nt++)
            #pragma unroll
            for (int j = 0; j < 4; j++)
                s[nt][j] = __uint_as_float(f2t(s[nt][j]));

        // ---- O += P V  (C-frag -> A-frag via quad shuffles) ----
        #pragma unroll
        for (int ks = 0; ks < 8; ks++) {
            unsigned a[4];
            float p0 = __shfl_sync(0xffffffffu, s[ks][0], sl0);
            float p1 = __shfl_sync(0xffffffffu, s[ks][1], sl0);
            a[0] = __float_as_uint(sub ? p1 : p0);
            float p2 = __shfl_sync(0xffffffffu, s[ks][2], sl0);
            float p3 = __shfl_sync(0xffffffffu, s[ks][3], sl0);
            a[1] = __float_as_uint(sub ? p3 : p2);
            float r0 = __shfl_sync(0xffffffffu, s[ks][0], sl2);
            float r1 = __shfl_sync(0xffffffffu, s[ks][1], sl2);
            a[2] = __float_as_uint(sub ? r1 : r0);
            float r2 = __shfl_sync(0xffffffffu, s[ks][2], sl2);
            float r3 = __shfl_sync(0xffffffffu, s[ks][3], sl2);
            a[3] = __float_as_uint(sub ? r3 : r2);

            #pragma unroll
            for (int nt = 0; nt < 8; nt++) {
                uint2 bp = sVp[(ks * 4 + tig) * PVP + nt * 8 + g];
                unsigned bb[2] = { bp.x, bp.y };
                mma8(o[nt], a, bb);
            }
        }
    }

    // ---- normalize and write context (b, s, d) ----
    const float inv0 = 1.0f / l0;
    const float inv1 = 1.0f / l1;
    float* op = g_ctx + (size_t)(b * Sv + qt * 128 + w * 16) * Dv + h * HDv;
    #pragma unroll
    for (int nt = 0; nt < 8; nt++) {
        const int cc = nt * 8 + 2 * tig;
        *(float2*)(op + (size_t)g * Dv + cc) =
            make_float2(o[nt][0] * inv0, o[nt][1] * inv0);
        *(float2*)(op + (size_t)(g + 8) * Dv + cc) =
            make_float2(o[nt][2] * inv1, o[nt][3] * inv1);
    }
}

// =============================================================================
extern "C" void kernel_launch(void* const* d_in, const int* in_sizes, int n_in,
                              void* d_out, int out_size)
{
    const float* x     = (const float*)d_in[0];
    const float* w_in  = (const float*)d_in[1];
    const float* b_in  = (const float*)d_in[2];
    const float* w_out = (const float*)d_in[3];
    const float* b_out = (const float*)d_in[4];
    const int*   mask  = (const int*)d_in[5];
    float* out = (float*)d_out;

    gemm_tc<N3v, 0><<<dim3(N3v / 128, Mv / 128), 256>>>(x, w_in, b_in, nullptr);
    attn_tc<<<dim3(Sv / 128, Hv, Bv), 256>>>(mask);
    gemm_tc<Dv, 1><<<dim3(Dv / 128, Mv / 128), 256>>>(nullptr, w_out, b_out, out);
}

// round 8
// speedup vs baseline: 2.7736x; 1.6035x over previous
#include <cuda_runtime.h>

// Problem constants
#define Bv 4
#define Sv 2048
#define Dv 1024
#define Hv 16
#define HDv 64
#define N3v 3072
#define Mv (Bv*Sv)   // 8192

// =============================================================================
// Pair-packed tf32 layouts. For a 32-wide k block, element k (0..31) lives in
// pair-row pr = ((k>>3)<<2)|(k&3), component (k>>2)&1  (pairs are (k, k+4)).
// This matches the MMA fragment reader: pair-row ks*4+tig -> k = ks*8+tig (+4).
// =============================================================================

// ---------------- scratch (device globals; no runtime allocation) -------------
__device__ __align__(256) unsigned g_q  [(size_t)Bv*Hv*Sv*HDv];      // tf32 bits, scaled
__device__ __align__(256) unsigned g_kp [(size_t)Bv*Hv*Sv*HDv];      // [bh][s][pr]{2}
__device__ __align__(256) unsigned g_vp [(size_t)Bv*Hv*Sv*HDv];      // [bh][kt][pr][hd]{2}
__device__ __align__(256) uint2    g_xp [(size_t)(Dv/32)*16*Mv];     // [k0b*16+pr][m]
__device__ __align__(256) uint2    g_wip[(size_t)(Dv/32)*16*N3v];    // [row][n]
__device__ __align__(256) uint2    g_wop[(size_t)(Dv/32)*16*Dv];
__device__ __align__(256) uint2    g_ctxp[(size_t)(Dv/32)*16*Mv];

// ---------------- helpers -----------------------------------------------------
__device__ __forceinline__ unsigned f2t(float f) {
    unsigned u;
    asm("cvt.rna.tf32.f32 %0, %1;" : "=r"(u) : "f"(f));
    return u;
}

__device__ __forceinline__ void mma8(float* c, const unsigned* a, const unsigned* b) {
    asm volatile(
        "mma.sync.aligned.m16n8k8.row.col.f32.tf32.tf32.f32 "
        "{%0,%1,%2,%3},{%4,%5,%6,%7},{%8,%9},{%0,%1,%2,%3};\n"
        : "+f"(c[0]), "+f"(c[1]), "+f"(c[2]), "+f"(c[3])
        : "r"(a[0]), "r"(a[1]), "r"(a[2]), "r"(a[3]),
          "r"(b[0]), "r"(b[1]));
}

__device__ __forceinline__ void cpa16(unsigned sa, const void* g) {
    asm volatile("cp.async.cg.shared.global [%0], [%1], 16;\n" :: "r"(sa), "l"(g));
}
__device__ __forceinline__ void cpa4(unsigned sa, const void* g) {
    asm volatile("cp.async.ca.shared.global [%0], [%1], 4;\n" :: "r"(sa), "l"(g));
}
__device__ __forceinline__ void cpa_commit() {
    asm volatile("cp.async.commit_group;\n");
}
template<int N> __device__ __forceinline__ void cpa_wait() {
    asm volatile("cp.async.wait_group %0;\n" :: "n"(N));
}

// =============================================================================
// Prepass: pack x (tiled transpose+pair) and weights into tf32 pair layout.
// =============================================================================
__global__ __launch_bounds__(256) void pack_x(const float* __restrict__ X)
{
    __shared__ float tx[64][33];
    const int t   = threadIdx.x;
    const int m0  = blockIdx.x * 64;
    const int k0b = blockIdx.y;

    const int r = t >> 2, c0 = (t & 3) * 8;
    #pragma unroll
    for (int j = 0; j < 8; j++)
        tx[r][c0 + j] = X[(size_t)(m0 + r) * Dv + k0b * 32 + c0 + j];
    __syncthreads();

    #pragma unroll
    for (int i = 0; i < 4; i++) {
        const int e  = t + 256 * i;
        const int pr = e >> 6, m = e & 63;
        const int klo = ((pr >> 2) << 3) | (pr & 3);
        g_xp[((size_t)(k0b * 16 + pr)) * Mv + m0 + m] =
            make_uint2(f2t(tx[m][klo]), f2t(tx[m][klo + 4]));
    }
}

template<int LDN>
__global__ __launch_bounds__(256) void pack_w(const float* __restrict__ W,
                                              uint2* __restrict__ Wp)
{
    const int n   = blockIdx.x * 256 + threadIdx.x;
    const int row = blockIdx.y;            // 0..511 = k0b*16 + pr
    const int pr  = row & 15;
    const int klo = (row >> 4) * 32 + (((pr >> 2) << 3) | (pr & 3));
    Wp[(size_t)row * LDN + n] =
        make_uint2(f2t(W[(size_t)klo * LDN + n]), f2t(W[(size_t)(klo + 4) * LDN + n]));
}

// =============================================================================
// QKV scatter epilogue helper -> packed tf32 layouts
// =============================================================================
__device__ __forceinline__ void qkv_store(int m, int n, float v, const float* __restrict__ bias) {
    v += bias[n];
    const int bb  = m >> 11;
    const int s   = m & 2047;
    const int sel = n >> 10;      // 0=q 1=k 2=v
    const int d   = n & 1023;
    const int h   = d >> 6;
    const int hd  = d & 63;
    const int bh  = bb * Hv + h;
    if (sel == 0) {
        g_q[((size_t)(bh * Sv + s)) * 64 + hd] = f2t(v * 0.125f);
    } else if (sel == 1) {
        const int pr = ((hd >> 3) << 2) | (hd & 3);
        const int cp = (hd >> 2) & 1;
        g_kp[(((size_t)(bh * Sv + s)) * 32 + pr) * 2 + cp] = f2t(v);
    } else {
        const int kt = s >> 6, st = s & 63;
        const int pr = ((st >> 3) << 2) | (st & 3);
        const int cp = (st >> 2) & 1;
        g_vp[((((size_t)(bh * 32 + kt)) * 32 + pr) * 64 + hd) * 2 + cp] = f2t(v);
    }
}

// =============================================================================
// Unified tf32 GEMM on pre-packed operands, cp.async 2-stage pipeline.
// 128x128 tile, BK=32, 256 threads (8 warps), warp tile 32x64. 2 CTAs/SM.
// smem pitch 132 uint2 (= 4 mod 16 bank-pairs -> LDS.64 conflict-free).
// EPI 0: scatter into packed q/k/v.  EPI 1: plain store + bias to `out`.
// =============================================================================
#define GPP 132
#define GT (16 * GPP)                 // one matrix tile in uint2
#define GEMM_SMEM (2 * 2 * GT * 8)    // 2 stages x (A+B) x 8B

template<int LDN, int EPI>
__global__ __launch_bounds__(256, 2) void gemm_tc(
    const uint2* __restrict__ Ag,
    const uint2* __restrict__ Bg,
    const float* __restrict__ bias,
    float* __restrict__ out)
{
    extern __shared__ uint2 smem[];   // [stage][A(GT) then B(GT)]
    const unsigned sbase = (unsigned)__cvta_generic_to_shared(smem);

    const int t    = threadIdx.x;
    const int w    = t >> 5, lane = t & 31;
    const int g    = lane >> 2, tig = lane & 3;
    const int row0 = blockIdx.y * 128;
    const int col0 = blockIdx.x * 128;
    const int m0w  = (w & 3) * 32;
    const int n0w  = (w >> 2) * 64;

    auto issue = [&](int st, int kb) {
        #pragma unroll
        for (int i = 0; i < 4; i++) {
            const int ca = t + 256 * i;
            const int rp = ca >> 6, mo = (ca & 63) * 2;
            cpa16(sbase + (unsigned)(st * 2 * GT + rp * GPP + mo) * 8,
                  Ag + (size_t)(kb * 16 + rp) * Mv + row0 + mo);
        }
        #pragma unroll
        for (int i = 0; i < 4; i++) {
            const int cb = t + 256 * i;
            const int rp = cb >> 6, no = (cb & 63) * 2;
            cpa16(sbase + (unsigned)(st * 2 * GT + GT + rp * GPP + no) * 8,
                  Bg + (size_t)(kb * 16 + rp) * LDN + col0 + no);
        }
        cpa_commit();
    };

    float c[2][8][4];
    #pragma unroll
    for (int mt = 0; mt < 2; mt++)
        #pragma unroll
        for (int nt = 0; nt < 8; nt++)
            #pragma unroll
            for (int j = 0; j < 4; j++) c[mt][nt][j] = 0.f;

    issue(0, 0);
    issue(1, 1);

    for (int kb = 0; kb < Dv / 32; kb++) {
        cpa_wait<1>();
        __syncthreads();

        const uint2* Ac = smem + (kb & 1) * 2 * GT;
        const uint2* Bc = Ac + GT;

        #pragma unroll
        for (int ks = 0; ks < 4; ks++) {
            unsigned a[2][4];
            #pragma unroll
            for (int mt = 0; mt < 2; mt++) {
                uint2 p0 = Ac[(ks * 4 + tig) * GPP + m0w + mt * 16 + g];
                uint2 p1 = Ac[(ks * 4 + tig) * GPP + m0w + mt * 16 + g + 8];
                a[mt][0] = p0.x; a[mt][1] = p1.x; a[mt][2] = p0.y; a[mt][3] = p1.y;
            }
            #pragma unroll
            for (int nt = 0; nt < 8; nt++) {
                uint2 bp = Bc[(ks * 4 + tig) * GPP + n0w + nt * 8 + g];
                unsigned bb[2] = { bp.x, bp.y };
                mma8(c[0][nt], a[0], bb);
                mma8(c[1][nt], a[1], bb);
            }
        }
        __syncthreads();
        if (kb + 2 < Dv / 32) issue(kb & 1, kb + 2);
    }

    if (EPI == 0) {
        #pragma unroll
        for (int mt = 0; mt < 2; mt++) {
            const int r0 = row0 + m0w + mt * 16 + g;
            const int r1 = r0 + 8;
            #pragma unroll
            for (int nt = 0; nt < 8; nt++) {
                const int n = col0 + n0w + nt * 8 + 2 * tig;
                qkv_store(r0, n,     c[mt][nt][0], bias);
                qkv_store(r0, n + 1, c[mt][nt][1], bias);
                qkv_store(r1, n,     c[mt][nt][2], bias);
                qkv_store(r1, n + 1, c[mt][nt][3], bias);
            }
        }
    } else {
        #pragma unroll
        for (int mt = 0; mt < 2; mt++) {
            const int r0 = row0 + m0w + mt * 16 + g;
            const int r1 = r0 + 8;
            #pragma unroll
            for (int nt = 0; nt < 8; nt++) {
                const int n = col0 + n0w + nt * 8 + 2 * tig;
                *(float2*)(out + (size_t)r0 * Dv + n) =
                    make_float2(c[mt][nt][0] + bias[n], c[mt][nt][1] + bias[n + 1]);
                *(float2*)(out + (size_t)r1 * Dv + n) =
                    make_float2(c[mt][nt][2] + bias[n], c[mt][nt][3] + bias[n + 1]);
            }
        }
    }
}

// =============================================================================
// tf32 flash attention on packed K/V, cp.async 2-stage, q-tile 128, 8 warps.
// Softmax fully register/shuffle resident. 2 CTAs/SM.
// =============================================================================
#define PKP 36
#define PVP 68
#define AST (64 * PKP + 32 * PVP)          // stage size in uint2 (K then V)
#define ATT_SMEM (2 * AST * 8)

__global__ __launch_bounds__(256, 2) void attn_tc(const int* __restrict__ mask)
{
    extern __shared__ uint2 asmem[];       // [stage][K(64*PKP) then V(32*PVP)]
    __shared__ int smask[2][64];
    const unsigned sbase = (unsigned)__cvta_generic_to_shared(asmem);

    const int t    = threadIdx.x;
    const int w    = t >> 5, lane = t & 31;
    const int g    = lane >> 2, tig = lane & 3;
    const int qt   = blockIdx.x;
    const int h    = blockIdx.y;
    const int b    = blockIdx.z;
    const int bh   = b * Hv + h;

    auto issue = [&](int st, int kt) {
        #pragma unroll
        for (int i = 0; i < 4; i++) {       // K tile: 64 rows x 32 uint2
            const int ck = t + 256 * i;
            const int rp = ck >> 4, off = (ck & 15) * 2;
            cpa16(sbase + (unsigned)(st * AST + rp * PKP + off) * 8,
                  g_kp + ((size_t)(bh * Sv + kt * 64 + rp) * 32 + off) * 2);
        }
        #pragma unroll
        for (int i = 0; i < 4; i++) {       // V tile: 32 pair-rows x 64 uint2
            const int ck = t + 256 * i;
            const int rp = ck >> 5, off = (ck & 31) * 2;
            cpa16(sbase + (unsigned)(st * AST + 64 * PKP + rp * PVP + off) * 8,
                  g_vp + (((size_t)(bh * 32 + kt) * 32 + rp) * 64 + off) * 2);
        }
        if (t < 64)
            cpa4((unsigned)__cvta_generic_to_shared(&smask[st][t]),
                 mask + b * Sv + kt * 64 + t);
        cpa_commit();
    };

    // ---- preload Q fragments (tf32 bits, rows qt*128 + w*16 .. +15) ----
    unsigned q[8][4];
    const unsigned* qp = g_q + ((size_t)bh * Sv + qt * 128 + w * 16) * 64;
    #pragma unroll
    for (int ks = 0; ks < 8; ks++) {
        q[ks][0] = qp[g * 64       + ks * 8 + tig];
        q[ks][1] = qp[(g + 8) * 64 + ks * 8 + tig];
        q[ks][2] = qp[g * 64       + ks * 8 + tig + 4];
        q[ks][3] = qp[(g + 8) * 64 + ks * 8 + tig + 4];
    }

    float o[8][4];
    #pragma unroll
    for (int nt = 0; nt < 8; nt++)
        #pragma unroll
        for (int j = 0; j < 4; j++) o[nt][j] = 0.f;

    float m0r = -1e30f, m1r = -1e30f, l0 = 0.f, l1 = 0.f;

    const int sub = tig & 1;
    const int sl0 = (lane & ~3) | (tig >> 1);
    const int sl2 = sl0 + 2;

    issue(0, 0);
    issue(1, 1);

    for (int kt = 0; kt < Sv / 64; kt++) {
        cpa_wait<1>();
        __syncthreads();

        const uint2* sKp = asmem + (kt & 1) * AST;
        const uint2* sVp = sKp + 64 * PKP;
        const int*   msk = smask[kt & 1];

        // ---- S = Q K^T ----
        float s[8][4];
        #pragma unroll
        for (int nt = 0; nt < 8; nt++)
            #pragma unroll
            for (int j = 0; j < 4; j++) s[nt][j] = 0.f;

        #pragma unroll
        for (int ks = 0; ks < 8; ks++) {
            #pragma unroll
            for (int nt = 0; nt < 8; nt++) {
                uint2 bp = sKp[(nt * 8 + g) * PKP + ks * 4 + tig];
                unsigned bb[2] = { bp.x, bp.y };
                mma8(s[nt], q[ks], bb);
            }
        }

        // ---- mask ----
        #pragma unroll
        for (int nt = 0; nt < 8; nt++) {
            const int cc = nt * 8 + 2 * tig;
            if (!msk[cc])     { s[nt][0] = -1e30f; s[nt][2] = -1e30f; }
            if (!msk[cc + 1]) { s[nt][1] = -1e30f; s[nt][3] = -1e30f; }
        }

        // ---- row max ----
        float mx0 = -1e30f, mx1 = -1e30f;
        #pragma unroll
        for (int nt = 0; nt < 8; nt++) {
            mx0 = fmaxf(mx0, fmaxf(s[nt][0], s[nt][1]));
            mx1 = fmaxf(mx1, fmaxf(s[nt][2], s[nt][3]));
        }
        mx0 = fmaxf(mx0, __shfl_xor_sync(0xffffffffu, mx0, 1));
        mx0 = fmaxf(mx0, __shfl_xor_sync(0xffffffffu, mx0, 2));
        mx1 = fmaxf(mx1, __shfl_xor_sync(0xffffffffu, mx1, 1));
        mx1 = fmaxf(mx1, __shfl_xor_sync(0xffffffffu, mx1, 2));

        const float mn0 = fmaxf(m0r, mx0);
        const float mn1 = fmaxf(m1r, mx1);
        const float cr0 = __expf(m0r - mn0);
        const float cr1 = __expf(m1r - mn1);
        m0r = mn0; m1r = mn1;

        // ---- exp + row sums ----
        float a0 = 0.f, a1 = 0.f;
        #pragma unroll
        for (int nt = 0; nt < 8; nt++) {
            s[nt][0] = __expf(s[nt][0] - mn0);
            s[nt][1] = __expf(s[nt][1] - mn0);
            s[nt][2] = __expf(s[nt][2] - mn1);
            s[nt][3] = __expf(s[nt][3] - mn1);
            a0 += s[nt][0] + s[nt][1];
            a1 += s[nt][2] + s[nt][3];
        }
        a0 += __shfl_xor_sync(0xffffffffu, a0, 1);
        a0 += __shfl_xor_sync(0xffffffffu, a0, 2);
        a1 += __shfl_xor_sync(0xffffffffu, a1, 1);
        a1 += __shfl_xor_sync(0xffffffffu, a1, 2);
        l0 = l0 * cr0 + a0;
        l1 = l1 * cr1 + a1;

        // ---- rescale O ----
        #pragma unroll
        for (int nt = 0; nt < 8; nt++) {
            o[nt][0] *= cr0; o[nt][1] *= cr0;
            o[nt][2] *= cr1; o[nt][3] *= cr1;
        }

        // ---- P -> tf32 (in place) ----
        #pragma unroll
        for (int nt = 0; nt < 8; nt++)
            #pragma unroll
            for (int j = 0; j < 4; j++)
                s[nt][j] = __uint_as_float(f2t(s[nt][j]));

        // ---- O += P V  (C-frag -> A-frag via quad shuffles) ----
        #pragma unroll
        for (int ks = 0; ks < 8; ks++) {
            unsigned a[4];
            float p0 = __shfl_sync(0xffffffffu, s[ks][0], sl0);
            float p1 = __shfl_sync(0xffffffffu, s[ks][1], sl0);
            a[0] = __float_as_uint(sub ? p1 : p0);
            float p2 = __shfl_sync(0xffffffffu, s[ks][2], sl0);
            float p3 = __shfl_sync(0xffffffffu, s[ks][3], sl0);
            a[1] = __float_as_uint(sub ? p3 : p2);
            float r0 = __shfl_sync(0xffffffffu, s[ks][0], sl2);
            float r1 = __shfl_sync(0xffffffffu, s[ks][1], sl2);
            a[2] = __float_as_uint(sub ? r1 : r0);
            float r2 = __shfl_sync(0xffffffffu, s[ks][2], sl2);
            float r3 = __shfl_sync(0xffffffffu, s[ks][3], sl2);
            a[3] = __float_as_uint(sub ? r3 : r2);

            #pragma unroll
            for (int nt = 0; nt < 8; nt++) {
                uint2 bp = sVp[(ks * 4 + tig) * PVP + nt * 8 + g];
                unsigned bb[2] = { bp.x, bp.y };
                mma8(o[nt], a, bb);
            }
        }

        __syncthreads();
        if (kt + 2 < Sv / 64) issue(kt & 1, kt + 2);
    }

    // ---- normalize and write packed ctx ----
    const float inv0 = 1.0f / l0;
    const float inv1 = 1.0f / l1;
    const int mrow0 = b * Sv + qt * 128 + w * 16 + g;
    unsigned* cx = (unsigned*)g_ctxp;
    #pragma unroll
    for (int nt = 0; nt < 8; nt++) {
        #pragma unroll
        for (int jj = 0; jj < 2; jj++) {
            const int d   = h * 64 + nt * 8 + 2 * tig + jj;
            const int k0b = d >> 5, kk = d & 31;
            const int pr  = ((kk >> 3) << 2) | (kk & 3);
            const int cp  = (kk >> 2) & 1;
            const size_t base = ((size_t)(k0b * 16 + pr)) * Mv;
            cx[(base + mrow0) * 2 + cp]     = f2t(o[nt][jj] * inv0);
            cx[(base + mrow0 + 8) * 2 + cp] = f2t(o[nt][2 + jj] * inv1);
        }
    }
}

// =============================================================================
extern "C" void kernel_launch(void* const* d_in, const int* in_sizes, int n_in,
                              void* d_out, int out_size)
{
    const float* x     = (const float*)d_in[0];
    const float* w_in  = (const float*)d_in[1];
    const float* b_in  = (const float*)d_in[2];
    const float* w_out = (const float*)d_in[3];
    const float* b_out = (const float*)d_in[4];
    const int*   mask  = (const int*)d_in[5];
    float* out = (float*)d_out;

    cudaFuncSetAttribute(gemm_tc<N3v, 0>, cudaFuncAttributeMaxDynamicSharedMemorySize, GEMM_SMEM);
    cudaFuncSetAttribute(gemm_tc<Dv, 1>,  cudaFuncAttributeMaxDynamicSharedMemorySize, GEMM_SMEM);
    cudaFuncSetAttribute(attn_tc,         cudaFuncAttributeMaxDynamicSharedMemorySize, ATT_SMEM);

    uint2 *xp, *wip, *wop, *ctxp;
    cudaGetSymbolAddress((void**)&xp,   g_xp);
    cudaGetSymbolAddress((void**)&wip,  g_wip);
    cudaGetSymbolAddress((void**)&wop,  g_wop);
    cudaGetSymbolAddress((void**)&ctxp, g_ctxp);

    pack_x<<<dim3(Mv / 64, Dv / 32), 256>>>(x);
    pack_w<N3v><<<dim3(N3v / 256, 512), 256>>>(w_in, wip);
    pack_w<Dv><<<dim3(Dv / 256, 512), 256>>>(w_out, wop);
    gemm_tc<N3v, 0><<<dim3(N3v / 128, Mv / 128), 256, GEMM_SMEM>>>(xp, wip, b_in, nullptr);
    attn_tc<<<dim3(Sv / 128, Hv, Bv), 256, ATT_SMEM>>>(mask);
    gemm_tc<Dv, 1><<<dim3(Dv / 128, Mv / 128), 256, GEMM_SMEM>>>(ctxp, wop, b_out, out);
}

// round 10
// speedup vs baseline: 3.4637x; 1.2488x over previous
#include <cuda_runtime.h>

// Problem constants
#define Bv 4
#define Sv 2048
#define Dv 1024
#define Hv 16
#define HDv 64
#define N3v 3072
#define Mv (Bv*Sv)   // 8192

// =============================================================================
// Pair-packed tf32 layouts. For a 32-wide k block, element k (0..31) lives in
// pair-row pr = ((k>>3)<<2)|(k&3), component (k>>2)&1  (pairs are (k, k+4)).
// =============================================================================

// ---------------- scratch (device globals; no runtime allocation) -------------
__device__ __align__(256) unsigned g_q  [(size_t)Bv*Hv*Sv*HDv];   // tf32 bits, *0.125*log2e
__device__ __align__(256) uint2    g_kp [(size_t)Bv*Hv*Sv*32];    // [bh][s][pr] pairs over hd
__device__ __align__(256) unsigned g_v  [(size_t)Bv*Hv*Sv*HDv];   // plain tf32 rows [bh][s][hd]
__device__ __align__(256) uint2    g_kc [(size_t)Bv*Hv*Sv*32];    // compacted K rows
__device__ __align__(256) uint2    g_vc [(size_t)Bv*Hv*Sv*32];    // compacted V pair tiles
__device__ __align__(256) int      g_kidx[Bv*Sv];
__device__ __align__(256) int      g_cnt[Bv];
// GEMM operands (pair-packed, R8 layout)
__device__ __align__(256) uint2    g_xp [(size_t)(Dv/32)*16*Mv];
__device__ __align__(256) uint2    g_wip[(size_t)(Dv/32)*16*N3v];
__device__ __align__(256) uint2    g_wop[(size_t)(Dv/32)*16*Dv];
__device__ __align__(256) uint2    g_ctxp[(size_t)(Dv/32)*16*Mv];

// ---------------- helpers -----------------------------------------------------
__device__ __forceinline__ unsigned f2t(float f) {
    unsigned u;
    asm("cvt.rna.tf32.f32 %0, %1;" : "=r"(u) : "f"(f));
    return u;
}
__device__ __forceinline__ float ex2(float x) {
    float y;
    asm("ex2.approx.f32 %0, %1;" : "=f"(y) : "f"(x));
    return y;
}
__device__ __forceinline__ void mma8(float* c, const unsigned* a, const unsigned* b) {
    asm volatile(
        "mma.sync.aligned.m16n8k8.row.col.f32.tf32.tf32.f32 "
        "{%0,%1,%2,%3},{%4,%5,%6,%7},{%8,%9},{%0,%1,%2,%3};\n"
        : "+f"(c[0]), "+f"(c[1]), "+f"(c[2]), "+f"(c[3])
        : "r"(a[0]), "r"(a[1]), "r"(a[2]), "r"(a[3]),
          "r"(b[0]), "r"(b[1]));
}
__device__ __forceinline__ void cpa16(unsigned sa, const void* g) {
    asm volatile("cp.async.cg.shared.global [%0], [%1], 16;\n" :: "r"(sa), "l"(g));
}
__device__ __forceinline__ void cpa_commit() {
    asm volatile("cp.async.commit_group;\n");
}
template<int N> __device__ __forceinline__ void cpa_wait() {
    asm volatile("cp.async.wait_group %0;\n" :: "n"(N));
}

// =============================================================================
// Mask scan: per batch, build compacted key index list + count.
// =============================================================================
__global__ __launch_bounds__(256) void mask_scan(const int* __restrict__ mask)
{
    __shared__ int part[256];
    const int b = blockIdx.x, t = threadIdx.x;
    int loc[8], c = 0;
    #pragma unroll
    for (int j = 0; j < 8; j++) {
        loc[j] = mask[b * Sv + t * 8 + j] > 0;
        c += loc[j];
    }
    part[t] = c;
    __syncthreads();
    int pre = 0;
    for (int i = 0; i < t; i++) pre += part[i];
    int p = pre;
    #pragma unroll
    for (int j = 0; j < 8; j++)
        if (loc[j]) g_kidx[b * Sv + (p++)] = t * 8 + j;
    if (t == 255) g_cnt[b] = pre + c;
}

// =============================================================================
// Compact K/V: gather unmasked keys into contiguous tiles.
// K: row copy (pairs over hd, gather-safe). V: build pairs over compacted keys.
// grid (32, Hv, Bv), 256 threads.
// =============================================================================
__global__ __launch_bounds__(256) void compact_kv()
{
    const int kt = blockIdx.x, h = blockIdx.y, b = blockIdx.z;
    const int cnt = g_cnt[b];
    if (kt * 64 >= cnt) return;
    const int bh = b * Hv + h;
    const int t = threadIdx.x;
    const int* kidx = g_kidx + b * Sv;

    // K: 64 rows x 32 uint2
    #pragma unroll
    for (int i = 0; i < 8; i++) {
        const int e = t + 256 * i;
        const int r = e >> 5, off = e & 31;
        const int ci = kt * 64 + r;
        uint2 val = make_uint2(0u, 0u);
        if (ci < cnt)
            val = g_kp[((size_t)bh * Sv + kidx[ci]) * 32 + off];
        g_kc[((size_t)bh * Sv + kt * 64 + r) * 32 + off] = val;
    }
    // V: 32 pair-rows x 64 uint2; pair-row rp -> keys (r0, r0+4) of compacted tile
    #pragma unroll
    for (int i = 0; i < 8; i++) {
        const int e = t + 256 * i;
        const int rp = e >> 6, hd = e & 63;
        const int r0 = ((rp >> 2) << 3) | (rp & 3);
        const int i0 = kt * 64 + r0, i1 = i0 + 4;
        unsigned v0 = 0u, v1 = 0u;
        if (i0 < cnt) v0 = g_v[((size_t)bh * Sv + kidx[i0]) * 64 + hd];
        if (i1 < cnt) v1 = g_v[((size_t)bh * Sv + kidx[i1]) * 64 + hd];
        g_vc[(((size_t)bh * 32 + kt) * 32 + rp) * 64 + hd] = make_uint2(v0, v1);
    }
}

// =============================================================================
// Prepass: pack x and weights into tf32 pair layout (R8).
// =============================================================================
__global__ __launch_bounds__(256) void pack_x(const float* __restrict__ X)
{
    __shared__ float tx[64][33];
    const int t   = threadIdx.x;
    const int m0  = blockIdx.x * 64;
    const int k0b = blockIdx.y;

    const int r = t >> 2, c0 = (t & 3) * 8;
    #pragma unroll
    for (int j = 0; j < 8; j++)
        tx[r][c0 + j] = X[(size_t)(m0 + r) * Dv + k0b * 32 + c0 + j];
    __syncthreads();

    #pragma unroll
    for (int i = 0; i < 4; i++) {
        const int e  = t + 256 * i;
        const int pr = e >> 6, m = e & 63;
        const int klo = ((pr >> 2) << 3) | (pr & 3);
        g_xp[((size_t)(k0b * 16 + pr)) * Mv + m0 + m] =
            make_uint2(f2t(tx[m][klo]), f2t(tx[m][klo + 4]));
    }
}

template<int LDN>
__global__ __launch_bounds__(256) void pack_w(const float* __restrict__ W,
                                              uint2* __restrict__ Wp)
{
    const int n   = blockIdx.x * 256 + threadIdx.x;
    const int row = blockIdx.y;            // 0..511 = k0b*16 + pr
    const int pr  = row & 15;
    const int klo = (row >> 4) * 32 + (((pr >> 2) << 3) | (pr & 3));
    Wp[(size_t)row * LDN + n] =
        make_uint2(f2t(W[(size_t)klo * LDN + n]), f2t(W[(size_t)(klo + 4) * LDN + n]));
}

// =============================================================================
// QKV scatter epilogue helper
// =============================================================================
__device__ __forceinline__ void qkv_store(int m, int n, float v, const float* __restrict__ bias) {
    v += bias[n];
    const int bb  = m >> 11;
    const int s   = m & 2047;
    const int sel = n >> 10;      // 0=q 1=k 2=v
    const int d   = n & 1023;
    const int h   = d >> 6;
    const int hd  = d & 63;
    const int bh  = bb * Hv + h;
    if (sel == 0) {
        g_q[((size_t)(bh * Sv + s)) * 64 + hd] = f2t(v * 0.18033688011112042f); // 0.125*log2e
    } else if (sel == 1) {
        const int pr = ((hd >> 3) << 2) | (hd & 3);
        const int cp = (hd >> 2) & 1;
        ((unsigned*)g_kp)[(((size_t)(bh * Sv + s)) * 32 + pr) * 2 + cp] = f2t(v);
    } else {
        g_v[((size_t)(bh * Sv + s)) * 64 + hd] = f2t(v);
    }
}

// =============================================================================
// Unified tf32 GEMM on pre-packed operands, cp.async 2-stage pipeline (R8).
// =============================================================================
#define GPP 132
#define GT (16 * GPP)
#define GEMM_SMEM (2 * 2 * GT * 8)

template<int LDN, int EPI>
__global__ __launch_bounds__(256, 2) void gemm_tc(
    const uint2* __restrict__ Ag,
    const uint2* __restrict__ Bg,
    const float* __restrict__ bias,
    float* __restrict__ out)
{
    extern __shared__ uint2 smem[];
    const unsigned sbase = (unsigned)__cvta_generic_to_shared(smem);

    const int t    = threadIdx.x;
    const int w    = t >> 5, lane = t & 31;
    const int g    = lane >> 2, tig = lane & 3;
    const int row0 = blockIdx.y * 128;
    const int col0 = blockIdx.x * 128;
    const int m0w  = (w & 3) * 32;
    const int n0w  = (w >> 2) * 64;

    auto issue = [&](int st, int kb) {
        #pragma unroll
        for (int i = 0; i < 4; i++) {
            const int ca = t + 256 * i;
            const int rp = ca >> 6, mo = (ca & 63) * 2;
            cpa16(sbase + (unsigned)(st * 2 * GT + rp * GPP + mo) * 8,
                  Ag + (size_t)(kb * 16 + rp) * Mv + row0 + mo);
        }
        #pragma unroll
        for (int i = 0; i < 4; i++) {
            const int cb = t + 256 * i;
            const int rp = cb >> 6, no = (cb & 63) * 2;
            cpa16(sbase + (unsigned)(st * 2 * GT + GT + rp * GPP + no) * 8,
                  Bg + (size_t)(kb * 16 + rp) * LDN + col0 + no);
        }
        cpa_commit();
    };

    float c[2][8][4];
    #pragma unroll
    for (int mt = 0; mt < 2; mt++)
        #pragma unroll
        for (int nt = 0; nt < 8; nt++)
            #pragma unroll
            for (int j = 0; j < 4; j++) c[mt][nt][j] = 0.f;

    issue(0, 0);
    issue(1, 1);

    for (int kb = 0; kb < Dv / 32; kb++) {
        cpa_wait<1>();
        __syncthreads();

        const uint2* Ac = smem + (kb & 1) * 2 * GT;
        const uint2* Bc = Ac + GT;

        #pragma unroll
        for (int ks = 0; ks < 4; ks++) {
            unsigned a[2][4];
            #pragma unroll
            for (int mt = 0; mt < 2; mt++) {
                uint2 p0 = Ac[(ks * 4 + tig) * GPP + m0w + mt * 16 + g];
                uint2 p1 = Ac[(ks * 4 + tig) * GPP + m0w + mt * 16 + g + 8];
                a[mt][0] = p0.x; a[mt][1] = p1.x; a[mt][2] = p0.y; a[mt][3] = p1.y;
            }
            #pragma unroll
            for (int nt = 0; nt < 8; nt++) {
                uint2 bp = Bc[(ks * 4 + tig) * GPP + n0w + nt * 8 + g];
                unsigned bb[2] = { bp.x, bp.y };
                mma8(c[0][nt], a[0], bb);
                mma8(c[1][nt], a[1], bb);
            }
        }
        __syncthreads();
        if (kb + 2 < Dv / 32) issue(kb & 1, kb + 2);
    }

    if (EPI == 0) {
        #pragma unroll
        for (int mt = 0; mt < 2; mt++) {
            const int r0 = row0 + m0w + mt * 16 + g;
            const int r1 = r0 + 8;
            #pragma unroll
            for (int nt = 0; nt < 8; nt++) {
                const int n = col0 + n0w + nt * 8 + 2 * tig;
                qkv_store(r0, n,     c[mt][nt][0], bias);
                qkv_store(r0, n + 1, c[mt][nt][1], bias);
                qkv_store(r1, n,     c[mt][nt][2], bias);
                qkv_store(r1, n + 1, c[mt][nt][3], bias);
            }
        }
    } else {
        #pragma unroll
        for (int mt = 0; mt < 2; mt++) {
            const int r0 = row0 + m0w + mt * 16 + g;
            const int r1 = r0 + 8;
            #pragma unroll
            for (int nt = 0; nt < 8; nt++) {
                const int n = col0 + n0w + nt * 8 + 2 * tig;
                *(float2*)(out + (size_t)r0 * Dv + n) =
                    make_float2(c[mt][nt][0] + bias[n], c[mt][nt][1] + bias[n + 1]);
                *(float2*)(out + (size_t)r1 * Dv + n) =
                    make_float2(c[mt][nt][2] + bias[n], c[mt][nt][3] + bias[n + 1]);
            }
        }
    }
}

// =============================================================================
// tf32 flash attention over COMPACTED keys. cp.async 2-stage, q-tile 128,
// 8 warps, softmax register/shuffle resident in log2 domain (ex2.approx).
// Tail tile handled by column predicate (no smem mask).
// =============================================================================
#define PKP 36
#define PVP 68
#define AST (64 * PKP + 32 * PVP)          // stage size in uint2 (K then V)
#define ATT_SMEM (2 * AST * 8)

__global__ __launch_bounds__(256, 2) void attn_tc()
{
    extern __shared__ uint2 asmem[];       // [stage][K(64*PKP) then V(32*PVP)]
    const unsigned sbase = (unsigned)__cvta_generic_to_shared(asmem);

    const int t    = threadIdx.x;
    const int w    = t >> 5, lane = t & 31;
    const int g    = lane >> 2, tig = lane & 3;
    const int qt   = blockIdx.x;
    const int h    = blockIdx.y;
    const int b    = blockIdx.z;
    const int bh   = b * Hv + h;

    const int cnt = g_cnt[b];
    const int nt_tiles = (cnt + 63) >> 6;

    auto issue = [&](int st, int kt) {
        #pragma unroll
        for (int i = 0; i < 4; i++) {       // K tile: 64 rows x 32 uint2
            const int ck = t + 256 * i;
            const int rp = ck >> 4, off = (ck & 15) * 2;
            cpa16(sbase + (unsigned)(st * AST + rp * PKP + off) * 8,
                  g_kc + (size_t)(bh * Sv + kt * 64 + rp) * 32 + off);
        }
        #pragma unroll
        for (int i = 0; i < 4; i++) {       // V tile: 32 pair-rows x 64 uint2
            const int ck = t + 256 * i;
            const int rp = ck >> 5, off = (ck & 31) * 2;
            cpa16(sbase + (unsigned)(st * AST + 64 * PKP + rp * PVP + off) * 8,
                  g_vc + ((size_t)(bh * 32 + kt) * 32 + rp) * 64 + off);
        }
        cpa_commit();
    };

    // ---- preload Q fragments (tf32 bits) ----
    unsigned q[8][4];
    const unsigned* qp = g_q + ((size_t)bh * Sv + qt * 128 + w * 16) * 64;
    #pragma unroll
    for (int ks = 0; ks < 8; ks++) {
        q[ks][0] = qp[g * 64       + ks * 8 + tig];
        q[ks][1] = qp[(g + 8) * 64 + ks * 8 + tig];
        q[ks][2] = qp[g * 64       + ks * 8 + tig + 4];
        q[ks][3] = qp[(g + 8) * 64 + ks * 8 + tig + 4];
    }

    float o[8][4];
    #pragma unroll
    for (int nt = 0; nt < 8; nt++)
        #pragma unroll
        for (int j = 0; j < 4; j++) o[nt][j] = 0.f;

    float m0r = -1e30f, m1r = -1e30f, l0 = 0.f, l1 = 0.f;

    const int sub = tig & 1;
    const int sl0 = (lane & ~3) | (tig >> 1);
    const int sl2 = sl0 + 2;

    issue(0, 0);
    if (nt_tiles > 1) issue(1, 1); else cpa_commit();

    for (int kt = 0; kt < nt_tiles; kt++) {
        cpa_wait<1>();
        __syncthreads();

        const uint2* sKp = asmem + (kt & 1) * AST;
        const uint2* sVp = sKp + 64 * PKP;

        // ---- S = Q K^T (log2 domain) ----
        float s[8][4];
        #pragma unroll
        for (int nt = 0; nt < 8; nt++)
            #pragma unroll
            for (int j = 0; j < 4; j++) s[nt][j] = 0.f;

        #pragma unroll
        for (int ks = 0; ks < 8; ks++) {
            #pragma unroll
            for (int nt = 0; nt < 8; nt++) {
                uint2 bp = sKp[(nt * 8 + g) * PKP + ks * 4 + tig];
                unsigned bb[2] = { bp.x, bp.y };
                mma8(s[nt], q[ks], bb);
            }
        }

        // ---- tail predicate (last tile only) ----
        const int limit = cnt - kt * 64;
        if (limit < 64) {
            #pragma unroll
            for (int nt = 0; nt < 8; nt++) {
                const int cc = nt * 8 + 2 * tig;
                if (cc >= limit)     { s[nt][0] = -1e30f; s[nt][2] = -1e30f; }
                if (cc + 1 >= limit) { s[nt][1] = -1e30f; s[nt][3] = -1e30f; }
            }
        }

        // ---- row max ----
        float mx0 = -1e30f, mx1 = -1e30f;
        #pragma unroll
        for (int nt = 0; nt < 8; nt++) {
            mx0 = fmaxf(mx0, fmaxf(s[nt][0], s[nt][1]));
            mx1 = fmaxf(mx1, fmaxf(s[nt][2], s[nt][3]));
        }
        mx0 = fmaxf(mx0, __shfl_xor_sync(0xffffffffu, mx0, 1));
        mx0 = fmaxf(mx0, __shfl_xor_sync(0xffffffffu, mx0, 2));
        mx1 = fmaxf(mx1, __shfl_xor_sync(0xffffffffu, mx1, 1));
        mx1 = fmaxf(mx1, __shfl_xor_sync(0xffffffffu, mx1, 2));

        const float mn0 = fmaxf(m0r, mx0);
        const float mn1 = fmaxf(m1r, mx1);
        const float cr0 = ex2(m0r - mn0);
        const float cr1 = ex2(m1r - mn1);
        m0r = mn0; m1r = mn1;

        // ---- exp2 + row sums ----
        float a0 = 0.f, a1 = 0.f;
        #pragma unroll
        for (int nt = 0; nt < 8; nt++) {
            s[nt][0] = ex2(s[nt][0] - mn0);
            s[nt][1] = ex2(s[nt][1] - mn0);
            s[nt][2] = ex2(s[nt][2] - mn1);
            s[nt][3] = ex2(s[nt][3] - mn1);
            a0 += s[nt][0] + s[nt][1];
            a1 += s[nt][2] + s[nt][3];
        }
        a0 += __shfl_xor_sync(0xffffffffu, a0, 1);
        a0 += __shfl_xor_sync(0xffffffffu, a0, 2);
        a1 += __shfl_xor_sync(0xffffffffu, a1, 1);
        a1 += __shfl_xor_sync(0xffffffffu, a1, 2);
        l0 = l0 * cr0 + a0;
        l1 = l1 * cr1 + a1;

        // ---- rescale O ----
        #pragma unroll
        for (int nt = 0; nt < 8; nt++) {
            o[nt][0] *= cr0; o[nt][1] *= cr0;
            o[nt][2] *= cr1; o[nt][3] *= cr1;
        }

        // ---- P -> tf32 (in place) ----
        #pragma unroll
        for (int nt = 0; nt < 8; nt++)
            #pragma unroll
            for (int j = 0; j < 4; j++)
                s[nt][j] = __uint_as_float(f2t(s[nt][j]));

        // ---- O += P V  (C-frag -> A-frag via quad shuffles) ----
        #pragma unroll
        for (int ks = 0; ks < 8; ks++) {
            unsigned a[4];
            float p0 = __shfl_sync(0xffffffffu, s[ks][0], sl0);
            float p1 = __shfl_sync(0xffffffffu, s[ks][1], sl0);
            a[0] = __float_as_uint(sub ? p1 : p0);
            float p2 = __shfl_sync(0xffffffffu, s[ks][2], sl0);
            float p3 = __shfl_sync(0xffffffffu, s[ks][3], sl0);
            a[1] = __float_as_uint(sub ? p3 : p2);
            float r0 = __shfl_sync(0xffffffffu, s[ks][0], sl2);
            float r1 = __shfl_sync(0xffffffffu, s[ks][1], sl2);
            a[2] = __float_as_uint(sub ? r1 : r0);
            float r2 = __shfl_sync(0xffffffffu, s[ks][2], sl2);
            float r3 = __shfl_sync(0xffffffffu, s[ks][3], sl2);
            a[3] = __float_as_uint(sub ? r3 : r2);

            #pragma unroll
            for (int nt = 0; nt < 8; nt++) {
                uint2 bp = sVp[(ks * 4 + tig) * PVP + nt * 8 + g];
                unsigned bb[2] = { bp.x, bp.y };
                mma8(o[nt], a, bb);
            }
        }

        __syncthreads();
        if (kt + 2 < nt_tiles) issue(kt & 1, kt + 2); else cpa_commit();
    }

    // ---- normalize and write packed ctx ----
    const float inv0 = 1.0f / l0;
    const float inv1 = 1.0f / l1;
    const int mrow0 = b * Sv + qt * 128 + w * 16 + g;
    unsigned* cx = (unsigned*)g_ctxp;
    #pragma unroll
    for (int nt = 0; nt < 8; nt++) {
        #pragma unroll
        for (int jj = 0; jj < 2; jj++) {
            const int d   = h * 64 + nt * 8 + 2 * tig + jj;
            const int k0b = d >> 5, kk = d & 31;
            const int pr  = ((kk >> 3) << 2) | (kk & 3);
            const int cp  = (kk >> 2) & 1;
            const size_t base = ((size_t)(k0b * 16 + pr)) * Mv;
            cx[(base + mrow0) * 2 + cp]     = f2t(o[nt][jj] * inv0);
            cx[(base + mrow0 + 8) * 2 + cp] = f2t(o[nt][2 + jj] * inv1);
        }
    }
}

// =============================================================================
extern "C" void kernel_launch(void* const* d_in, const int* in_sizes, int n_in,
                              void* d_out, int out_size)
{
    const float* x     = (const float*)d_in[0];
    const float* w_in  = (const float*)d_in[1];
    const float* b_in  = (const float*)d_in[2];
    const float* w_out = (const float*)d_in[3];
    const float* b_out = (const float*)d_in[4];
    const int*   mask  = (const int*)d_in[5];
    float* out = (float*)d_out;

    cudaFuncSetAttribute(gemm_tc<N3v, 0>, cudaFuncAttributeMaxDynamicSharedMemorySize, GEMM_SMEM);
    cudaFuncSetAttribute(gemm_tc<Dv, 1>,  cudaFuncAttributeMaxDynamicSharedMemorySize, GEMM_SMEM);
    cudaFuncSetAttribute(attn_tc,         cudaFuncAttributeMaxDynamicSharedMemorySize, ATT_SMEM);

    uint2 *xp, *wip, *wop, *ctxp;
    cudaGetSymbolAddress((void**)&xp,   g_xp);
    cudaGetSymbolAddress((void**)&wip,  g_wip);
    cudaGetSymbolAddress((void**)&wop,  g_wop);
    cudaGetSymbolAddress((void**)&ctxp, g_ctxp);

    mask_scan<<<Bv, 256>>>(mask);
    pack_x<<<dim3(Mv / 64, Dv / 32), 256>>>(x);
    pack_w<N3v><<<dim3(N3v / 256, 512), 256>>>(w_in, wip);
    pack_w<Dv><<<dim3(Dv / 256, 512), 256>>>(w_out, wop);
    gemm_tc<N3v, 0><<<dim3(N3v / 128, Mv / 128), 256, GEMM_SMEM>>>(xp, wip, b_in, nullptr);
    compact_kv<<<dim3(32, Hv, Bv), 256>>>();
    attn_tc<<<dim3(Sv / 128, Hv, Bv), 256, ATT_SMEM>>>();
    gemm_tc<Dv, 1><<<dim3(Dv / 128, Mv / 128), 256, GEMM_SMEM>>>(ctxp, wop, b_out, out);
}

// round 11
// speedup vs baseline: 6.7424x; 1.9466x over previous
#include <cuda_runtime.h>
#include <cuda_fp16.h>

// Problem constants
#define Bv 4
#define Sv 2048
#define Dv 1024
#define Hv 16
#define HDv 64
#define N3v 3072
#define Mv (Bv*Sv)   // 8192

// =============================================================================
// fp16 pair-packed layouts. A 32-bit word holds halves (2w, 2w+1) of the k dim.
// For a 64-wide k block split into 4 mma k-steps (k=16 each), pair-row
// pr = ks*4 + tig holds uint2 = (word ks*8+tig, word ks*8+tig+4), matching the
// m16n8k16 fragment reader exactly.
// =============================================================================

// ---------------- scratch (device globals; no runtime allocation) -------------
__device__ __align__(256) unsigned g_q [(size_t)Bv*Hv*Sv*32];     // fp16x2 rows, *0.125*log2e
__device__ __align__(256) uint2    g_kp[(size_t)Bv*Hv*Sv*16];     // [bh][s][pr] pairs over hd-words
__device__ __align__(256) unsigned g_v [(size_t)Bv*Hv*Sv*32];     // fp16x2 rows [bh][s][hw]
__device__ __align__(256) uint2    g_kc[(size_t)Bv*Hv*Sv*16];     // compacted K rows
__device__ __align__(256) uint2    g_vc[(size_t)Bv*Hv*32*16*64];  // compacted V pair tiles
__device__ __align__(256) int      g_kidx[Bv*Sv];
__device__ __align__(256) int      g_cnt[Bv];
// GEMM operands: [k0b(k/64)*16 + pr][m or n] uint2
__device__ __align__(256) uint2    g_xp [(size_t)(Dv/64)*16*Mv];
__device__ __align__(256) uint2    g_wip[(size_t)(Dv/64)*16*N3v];
__device__ __align__(256) uint2    g_wop[(size_t)(Dv/64)*16*Dv];
__device__ __align__(256) uint2    g_ctxp[(size_t)(Dv/64)*16*Mv];

// ---------------- helpers -----------------------------------------------------
__device__ __forceinline__ unsigned pk2(float a, float b) {
    __half2 h = __floats2half2_rn(a, b);
    return *(unsigned*)&h;
}
__device__ __forceinline__ float ex2(float x) {
    float y;
    asm("ex2.approx.f32 %0, %1;" : "=f"(y) : "f"(x));
    return y;
}
__device__ __forceinline__ void mma16(float* c, const unsigned* a, const unsigned* b) {
    asm volatile(
        "mma.sync.aligned.m16n8k16.row.col.f32.f16.f16.f32 "
        "{%0,%1,%2,%3},{%4,%5,%6,%7},{%8,%9},{%0,%1,%2,%3};\n"
        : "+f"(c[0]), "+f"(c[1]), "+f"(c[2]), "+f"(c[3])
        : "r"(a[0]), "r"(a[1]), "r"(a[2]), "r"(a[3]),
          "r"(b[0]), "r"(b[1]));
}
__device__ __forceinline__ void cpa16(unsigned sa, const void* g) {
    asm volatile("cp.async.cg.shared.global [%0], [%1], 16;\n" :: "r"(sa), "l"(g));
}
__device__ __forceinline__ void cpa_commit() {
    asm volatile("cp.async.commit_group;\n");
}
template<int N> __device__ __forceinline__ void cpa_wait() {
    asm volatile("cp.async.wait_group %0;\n" :: "n"(N));
}

// =============================================================================
// Mask scan: per batch, build compacted key index list + count.
// =============================================================================
__global__ __launch_bounds__(256) void mask_scan(const int* __restrict__ mask)
{
    __shared__ int part[256];
    const int b = blockIdx.x, t = threadIdx.x;
    int loc[8], c = 0;
    #pragma unroll
    for (int j = 0; j < 8; j++) {
        loc[j] = mask[b * Sv + t * 8 + j] > 0;
        c += loc[j];
    }
    part[t] = c;
    __syncthreads();
    int pre = 0;
    for (int i = 0; i < t; i++) pre += part[i];
    int p = pre;
    #pragma unroll
    for (int j = 0; j < 8; j++)
        if (loc[j]) g_kidx[b * Sv + (p++)] = t * 8 + j;
    if (t == 255) g_cnt[b] = pre + c;
}

// =============================================================================
// Compact K/V. K: row gather (16 uint2/row). V: build key-paired words from
// gathered rows. grid (32, Hv, Bv), 256 threads.
// =============================================================================
__global__ __launch_bounds__(256) void compact_kv()
{
    const int kt = blockIdx.x, h = blockIdx.y, b = blockIdx.z;
    const int cnt = g_cnt[b];
    if (kt * 64 >= cnt) return;
    const int bh = b * Hv + h;
    const int t = threadIdx.x;
    const int* kidx = g_kidx + b * Sv;

    // K: 64 rows x 16 uint2
    #pragma unroll
    for (int i = 0; i < 4; i++) {
        const int e = t + 256 * i;
        const int r = e >> 4, off = e & 15;
        const int ci = kt * 64 + r;
        uint2 val = make_uint2(0u, 0u);
        if (ci < cnt)
            val = g_kp[((size_t)bh * Sv + kidx[ci]) * 16 + off];
        g_kc[((size_t)bh * Sv + kt * 64 + r) * 16 + off] = val;
    }
    // V: 16 pair-rows x 64 uint2; pr packs key-words (8ks+tig, +4); each key-word
    // kw = keys (2kw, 2kw+1) of the compacted tile.
    #pragma unroll
    for (int i = 0; i < 2; i++) {
        const int e = t + 256 * i;
        const int pr = e >> 5, hwp = e & 31;     // hd pair (2hwp, 2hwp+1)
        const int kw0 = ((pr >> 2) << 3) | (pr & 3);
        const int kl0 = kt * 64 + 2 * kw0;       // keys kl0, kl0+1, kl0+8, kl0+9
        unsigned va = 0u, vb = 0u, vc = 0u, vd = 0u;
        if (kl0     < cnt) va = g_v[((size_t)bh * Sv + kidx[kl0])     * 32 + hwp];
        if (kl0 + 1 < cnt) vb = g_v[((size_t)bh * Sv + kidx[kl0 + 1]) * 32 + hwp];
        if (kl0 + 8 < cnt) vc = g_v[((size_t)bh * Sv + kidx[kl0 + 8]) * 32 + hwp];
        if (kl0 + 9 < cnt) vd = g_v[((size_t)bh * Sv + kidx[kl0 + 9]) * 32 + hwp];
        const size_t base = ((size_t)(bh * 32 + kt) * 16 + pr) * 64;
        g_vc[base + 2 * hwp]     = make_uint2(__byte_perm(va, vb, 0x5410),
                                              __byte_perm(vc, vd, 0x5410));
        g_vc[base + 2 * hwp + 1] = make_uint2(__byte_perm(va, vb, 0x7632),
                                              __byte_perm(vc, vd, 0x7632));
    }
}

// =============================================================================
// Prepass: pack x and weights into fp16 pair layout.
// =============================================================================
__global__ __launch_bounds__(256) void pack_x(const float* __restrict__ X)
{
    __shared__ float tx[64][65];
    const int t   = threadIdx.x;
    const int m0  = blockIdx.x * 64;
    const int k0b = blockIdx.y;

    const int r = t >> 2, c0 = (t & 3) * 16;
    #pragma unroll
    for (int j = 0; j < 4; j++) {
        float4 v = *(const float4*)(X + (size_t)(m0 + r) * Dv + k0b * 64 + c0 + 4 * j);
        tx[r][c0 + 4*j] = v.x; tx[r][c0 + 4*j+1] = v.y;
        tx[r][c0 + 4*j+2] = v.z; tx[r][c0 + 4*j+3] = v.w;
    }
    __syncthreads();

    #pragma unroll
    for (int i = 0; i < 4; i++) {
        const int e  = t + 256 * i;
        const int pr = e >> 6, m = e & 63;
        const int w0 = ((pr >> 2) << 3) | (pr & 3);
        g_xp[((size_t)(k0b * 16 + pr)) * Mv + m0 + m] =
            make_uint2(pk2(tx[m][2*w0], tx[m][2*w0 + 1]),
                       pk2(tx[m][2*w0 + 8], tx[m][2*w0 + 9]));
    }
}

template<int LDN>
__global__ __launch_bounds__(256) void pack_w(const float* __restrict__ W,
                                              uint2* __restrict__ Wp)
{
    const int n   = blockIdx.x * 256 + threadIdx.x;
    const int row = blockIdx.y;            // 0..255 = k0b*16 + pr
    const int pr  = row & 15;
    const int w0  = ((pr >> 2) << 3) | (pr & 3);
    const int k0  = (row >> 4) * 64 + 2 * w0;
    Wp[(size_t)row * LDN + n] =
        make_uint2(pk2(W[(size_t)k0 * LDN + n],       W[(size_t)(k0 + 1) * LDN + n]),
                   pk2(W[(size_t)(k0 + 8) * LDN + n], W[(size_t)(k0 + 9) * LDN + n]));
}

// =============================================================================
// QKV pair-store epilogue helper (n even, stores halves (n, n+1))
// =============================================================================
__device__ __forceinline__ void qkv_store2(int m, int n, float v0, float v1,
                                           const float* __restrict__ bias) {
    v0 += bias[n]; v1 += bias[n + 1];
    const int bb  = m >> 11;
    const int s   = m & 2047;
    const int sel = n >> 10;      // 0=q 1=k 2=v
    const int d   = n & 1023;
    const int h   = d >> 6;
    const int hw  = (d & 63) >> 1;
    const int bh  = bb * Hv + h;
    if (sel == 0) {
        const float qs = 0.18033688011112042f;   // 0.125*log2e
        g_q[((size_t)(bh * Sv + s)) * 32 + hw] = pk2(v0 * qs, v1 * qs);
    } else if (sel == 1) {
        const int ks = hw >> 3, wi = hw & 7;
        const int comp = wi >> 2, tg = wi & 3;
        ((unsigned*)g_kp)[(((size_t)(bh * Sv + s)) * 16 + ks * 4 + tg) * 2 + comp] = pk2(v0, v1);
    } else {
        g_v[((size_t)(bh * Sv + s)) * 32 + hw] = pk2(v0, v1);
    }
}

// =============================================================================
// Unified fp16 GEMM on pre-packed operands, cp.async 2-stage pipeline.
// 128x128 tile, BK=64, 256 threads (8 warps), warp tile 32x64. 2 CTAs/SM.
// =============================================================================
#define GPP 132
#define GT (16 * GPP)
#define GEMM_SMEM (2 * 2 * GT * 8)

template<int LDN, int EPI>
__global__ __launch_bounds__(256, 2) void gemm_tc(
    const uint2* __restrict__ Ag,
    const uint2* __restrict__ Bg,
    const float* __restrict__ bias,
    float* __restrict__ out)
{
    extern __shared__ uint2 smem[];
    const unsigned sbase = (unsigned)__cvta_generic_to_shared(smem);

    const int t    = threadIdx.x;
    const int w    = t >> 5, lane = t & 31;
    const int g    = lane >> 2, tig = lane & 3;
    const int row0 = blockIdx.y * 128;
    const int col0 = blockIdx.x * 128;
    const int m0w  = (w & 3) * 32;
    const int n0w  = (w >> 2) * 64;

    auto issue = [&](int st, int kb) {
        #pragma unroll
        for (int i = 0; i < 4; i++) {
            const int ca = t + 256 * i;
            const int rp = ca >> 6, mo = (ca & 63) * 2;
            cpa16(sbase + (unsigned)(st * 2 * GT + rp * GPP + mo) * 8,
                  Ag + (size_t)(kb * 16 + rp) * Mv + row0 + mo);
        }
        #pragma unroll
        for (int i = 0; i < 4; i++) {
            const int cb = t + 256 * i;
            const int rp = cb >> 6, no = (cb & 63) * 2;
            cpa16(sbase + (unsigned)(st * 2 * GT + GT + rp * GPP + no) * 8,
                  Bg + (size_t)(kb * 16 + rp) * LDN + col0 + no);
        }
        cpa_commit();
    };

    float c[2][8][4];
    #pragma unroll
    for (int mt = 0; mt < 2; mt++)
        #pragma unroll
        for (int nt = 0; nt < 8; nt++)
            #pragma unroll
            for (int j = 0; j < 4; j++) c[mt][nt][j] = 0.f;

    issue(0, 0);
    issue(1, 1);

    for (int kb = 0; kb < Dv / 64; kb++) {
        cpa_wait<1>();
        __syncthreads();

        const uint2* Ac = smem + (kb & 1) * 2 * GT;
        const uint2* Bc = Ac + GT;

        #pragma unroll
        for (int ks = 0; ks < 4; ks++) {
            unsigned a[2][4];
            #pragma unroll
            for (int mt = 0; mt < 2; mt++) {
                uint2 p0 = Ac[(ks * 4 + tig) * GPP + m0w + mt * 16 + g];
                uint2 p1 = Ac[(ks * 4 + tig) * GPP + m0w + mt * 16 + g + 8];
                a[mt][0] = p0.x; a[mt][1] = p1.x; a[mt][2] = p0.y; a[mt][3] = p1.y;
            }
            #pragma unroll
            for (int nt = 0; nt < 8; nt++) {
                uint2 bp = Bc[(ks * 4 + tig) * GPP + n0w + nt * 8 + g];
                unsigned bb[2] = { bp.x, bp.y };
                mma16(c[0][nt], a[0], bb);
                mma16(c[1][nt], a[1], bb);
            }
        }
        __syncthreads();
        if (kb + 2 < Dv / 64) issue(kb & 1, kb + 2);
    }

    if (EPI == 0) {
        #pragma unroll
        for (int mt = 0; mt < 2; mt++) {
            const int r0 = row0 + m0w + mt * 16 + g;
            const int r1 = r0 + 8;
            #pragma unroll
            for (int nt = 0; nt < 8; nt++) {
                const int n = col0 + n0w + nt * 8 + 2 * tig;
                qkv_store2(r0, n, c[mt][nt][0], c[mt][nt][1], bias);
                qkv_store2(r1, n, c[mt][nt][2], c[mt][nt][3], bias);
            }
        }
    } else {
        #pragma unroll
        for (int mt = 0; mt < 2; mt++) {
            const int r0 = row0 + m0w + mt * 16 + g;
            const int r1 = r0 + 8;
            #pragma unroll
            for (int nt = 0; nt < 8; nt++) {
                const int n = col0 + n0w + nt * 8 + 2 * tig;
                *(float2*)(out + (size_t)r0 * Dv + n) =
                    make_float2(c[mt][nt][0] + bias[n], c[mt][nt][1] + bias[n + 1]);
                *(float2*)(out + (size_t)r1 * Dv + n) =
                    make_float2(c[mt][nt][2] + bias[n], c[mt][nt][3] + bias[n + 1]);
            }
        }
    }
}

// =============================================================================
// fp16 flash attention over COMPACTED keys. cp.async 2-stage, q-tile 128,
// 8 warps, log2-domain softmax, shuffle-free P->A conversion. 2 CTAs/SM.
// =============================================================================
#define PK2 20
#define PV2 68
#define AST2 (64 * PK2 + 16 * PV2)         // stage size in uint2 (K then V)
#define ATT_SMEM (2 * AST2 * 8)

__global__ __launch_bounds__(256, 2) void attn_tc()
{
    extern __shared__ uint2 asmem[];       // [stage][K(64*PK2) then V(16*PV2)]
    const unsigned sbase = (unsigned)__cvta_generic_to_shared(asmem);

    const int t    = threadIdx.x;
    const int w    = t >> 5, lane = t & 31;
    const int g    = lane >> 2, tig = lane & 3;
    const int qt   = blockIdx.x;
    const int h    = blockIdx.y;
    const int b    = blockIdx.z;
    const int bh   = b * Hv + h;

    const int cnt = g_cnt[b];
    const int nt_tiles = (cnt + 63) >> 6;

    auto issue = [&](int st, int kt) {
        #pragma unroll
        for (int i = 0; i < 2; i++) {       // K tile: 64 keys x 16 uint2
            const int e = t + 256 * i;
            const int key = e >> 3, off = (e & 7) * 2;
            cpa16(sbase + (unsigned)(st * AST2 + key * PK2 + off) * 8,
                  g_kc + (size_t)(bh * Sv + kt * 64 + key) * 16 + off);
        }
        #pragma unroll
        for (int i = 0; i < 2; i++) {       // V tile: 16 pr x 64 uint2
            const int e = t + 256 * i;
            const int pr = e >> 5, off = (e & 31) * 2;
            cpa16(sbase + (unsigned)(st * AST2 + 64 * PK2 + pr * PV2 + off) * 8,
                  g_vc + ((size_t)(bh * 32 + kt) * 16 + pr) * 64 + off);
        }
        cpa_commit();
    };

    // ---- preload Q fragments (fp16x2 words) ----
    unsigned q[4][4];
    const unsigned* qp = g_q + ((size_t)bh * Sv + qt * 128 + w * 16) * 32;
    #pragma unroll
    for (int ks = 0; ks < 4; ks++) {
        q[ks][0] = qp[g * 32       + ks * 8 + tig];
        q[ks][1] = qp[(g + 8) * 32 + ks * 8 + tig];
        q[ks][2] = qp[g * 32       + ks * 8 + tig + 4];
        q[ks][3] = qp[(g + 8) * 32 + ks * 8 + tig + 4];
    }

    float o[8][4];
    #pragma unroll
    for (int nt = 0; nt < 8; nt++)
        #pragma unroll
        for (int j = 0; j < 4; j++) o[nt][j] = 0.f;

    float m0r = -1e30f, m1r = -1e30f, l0 = 0.f, l1 = 0.f;

    issue(0, 0);
    if (nt_tiles > 1) issue(1, 1); else cpa_commit();

    for (int kt = 0; kt < nt_tiles; kt++) {
        cpa_wait<1>();
        __syncthreads();

        const uint2* sKp = asmem + (kt & 1) * AST2;
        const uint2* sVp = sKp + 64 * PK2;

        // ---- S = Q K^T (log2 domain) ----
        float s[8][4];
        #pragma unroll
        for (int nt = 0; nt < 8; nt++)
            #pragma unroll
            for (int j = 0; j < 4; j++) s[nt][j] = 0.f;

        #pragma unroll
        for (int ks = 0; ks < 4; ks++) {
            #pragma unroll
            for (int nt = 0; nt < 8; nt++) {
                uint2 bp = sKp[(nt * 8 + g) * PK2 + ks * 4 + tig];
                unsigned bb[2] = { bp.x, bp.y };
                mma16(s[nt], q[ks], bb);
            }
        }

        // ---- tail predicate (last tile only) ----
        const int limit = cnt - kt * 64;
        if (limit < 64) {
            #pragma unroll
            for (int nt = 0; nt < 8; nt++) {
                const int cc = nt * 8 + 2 * tig;
                if (cc >= limit)     { s[nt][0] = -1e30f; s[nt][2] = -1e30f; }
                if (cc + 1 >= limit) { s[nt][1] = -1e30f; s[nt][3] = -1e30f; }
            }
        }

        // ---- row max ----
        float mx0 = -1e30f, mx1 = -1e30f;
        #pragma unroll
        for (int nt = 0; nt < 8; nt++) {
            mx0 = fmaxf(mx0, fmaxf(s[nt][0], s[nt][1]));
            mx1 = fmaxf(mx1, fmaxf(s[nt][2], s[nt][3]));
        }
        mx0 = fmaxf(mx0, __shfl_xor_sync(0xffffffffu, mx0, 1));
        mx0 = fmaxf(mx0, __shfl_xor_sync(0xffffffffu, mx0, 2));
        mx1 = fmaxf(mx1, __shfl_xor_sync(0xffffffffu, mx1, 1));
        mx1 = fmaxf(mx1, __shfl_xor_sync(0xffffffffu, mx1, 2));

        const float mn0 = fmaxf(m0r, mx0);
        const float mn1 = fmaxf(m1r, mx1);
        const float cr0 = ex2(m0r - mn0);
        const float cr1 = ex2(m1r - mn1);
        m0r = mn0; m1r = mn1;

        // ---- exp2 + row sums ----
        float a0 = 0.f, a1 = 0.f;
        #pragma unroll
        for (int nt = 0; nt < 8; nt++) {
            s[nt][0] = ex2(s[nt][0] - mn0);
            s[nt][1] = ex2(s[nt][1] - mn0);
            s[nt][2] = ex2(s[nt][2] - mn1);
            s[nt][3] = ex2(s[nt][3] - mn1);
            a0 += s[nt][0] + s[nt][1];
            a1 += s[nt][2] + s[nt][3];
        }
        a0 += __shfl_xor_sync(0xffffffffu, a0, 1);
        a0 += __shfl_xor_sync(0xffffffffu, a0, 2);
        a1 += __shfl_xor_sync(0xffffffffu, a1, 1);
        a1 += __shfl_xor_sync(0xffffffffu, a1, 2);
        l0 = l0 * cr0 + a0;
        l1 = l1 * cr1 + a1;

        // ---- rescale O ----
        #pragma unroll
        for (int nt = 0; nt < 8; nt++) {
            o[nt][0] *= cr0; o[nt][1] *= cr0;
            o[nt][2] *= cr1; o[nt][3] *= cr1;
        }

        // ---- O += P V  (shuffle-free: C-frag cols == fp16 A-frag halves) ----
        #pragma unroll
        for (int ks = 0; ks < 4; ks++) {
            unsigned a[4];
            a[0] = pk2(s[2*ks][0],     s[2*ks][1]);
            a[1] = pk2(s[2*ks][2],     s[2*ks][3]);
            a[2] = pk2(s[2*ks + 1][0], s[2*ks + 1][1]);
            a[3] = pk2(s[2*ks + 1][2], s[2*ks + 1][3]);
            #pragma unroll
            for (int nt = 0; nt < 8; nt++) {
                uint2 bp = sVp[(ks * 4 + tig) * PV2 + nt * 8 + g];
                unsigned bb[2] = { bp.x, bp.y };
                mma16(o[nt], a, bb);
            }
        }

        __syncthreads();
        if (kt + 2 < nt_tiles) issue(kt & 1, kt + 2); else cpa_commit();
    }

    // ---- normalize and write packed ctx ----
    const float inv0 = 1.0f / l0;
    const float inv1 = 1.0f / l1;
    const int mrow0 = b * Sv + qt * 128 + w * 16 + g;
    unsigned* cx = (unsigned*)g_ctxp;
    #pragma unroll
    for (int nt = 0; nt < 8; nt++) {
        const int d0   = h * 64 + nt * 8 + 2 * tig;
        const int hw   = d0 >> 1;
        const int k0b  = d0 >> 6;
        const int lw   = hw & 31;
        const int ks   = lw >> 3, wi = lw & 7;
        const int comp = wi >> 2, tg = wi & 3;
        const size_t base = ((size_t)(k0b * 16 + ks * 4 + tg)) * Mv;
        cx[(base + mrow0) * 2 + comp]     = pk2(o[nt][0] * inv0, o[nt][1] * inv0);
        cx[(base + mrow0 + 8) * 2 + comp] = pk2(o[nt][2] * inv1, o[nt][3] * inv1);
    }
}

// =============================================================================
extern "C" void kernel_launch(void* const* d_in, const int* in_sizes, int n_in,
                              void* d_out, int out_size)
{
    const float* x     = (const float*)d_in[0];
    const float* w_in  = (const float*)d_in[1];
    const float* b_in  = (const float*)d_in[2];
    const float* w_out = (const float*)d_in[3];
    const float* b_out = (const float*)d_in[4];
    const int*   mask  = (const int*)d_in[5];
    float* out = (float*)d_out;

    cudaFuncSetAttribute(gemm_tc<N3v, 0>, cudaFuncAttributeMaxDynamicSharedMemorySize, GEMM_SMEM);
    cudaFuncSetAttribute(gemm_tc<Dv, 1>,  cudaFuncAttributeMaxDynamicSharedMemorySize, GEMM_SMEM);
    cudaFuncSetAttribute(attn_tc,         cudaFuncAttributeMaxDynamicSharedMemorySize, ATT_SMEM);

    uint2 *xp, *wip, *wop, *ctxp;
    cudaGetSymbolAddress((void**)&xp,   g_xp);
    cudaGetSymbolAddress((void**)&wip,  g_wip);
    cudaGetSymbolAddress((void**)&wop,  g_wop);
    cudaGetSymbolAddress((void**)&ctxp, g_ctxp);

    mask_scan<<<Bv, 256>>>(mask);
    pack_x<<<dim3(Mv / 64, Dv / 64), 256>>>(x);
    pack_w<N3v><<<dim3(N3v / 256, 256), 256>>>(w_in, wip);
    pack_w<Dv><<<dim3(Dv / 256, 256), 256>>>(w_out, wop);
    gemm_tc<N3v, 0><<<dim3(N3v / 128, Mv / 128), 256, GEMM_SMEM>>>(xp, wip, b_in, nullptr);
    compact_kv<<<dim3(32, Hv, Bv), 256>>>();
    attn_tc<<<dim3(Sv / 128, Hv, Bv), 256, ATT_SMEM>>>();
    gemm_tc<Dv, 1><<<dim3(Dv / 128, Mv / 128), 256, GEMM_SMEM>>>(ctxp, wop, b_out, out);
}

// round 12
// speedup vs baseline: 7.7365x; 1.1474x over previous
#include <cuda_runtime.h>
#include <cuda_fp16.h>

// Problem constants
#define Bv 4
#define Sv 2048
#define Dv 1024
#define Hv 16
#define HDv 64
#define N3v 3072
#define Mv (Bv*Sv)   // 8192

// =============================================================================
// All MMA operands live in gmem as SW128-swizzled SMEM-image tiles:
// tile = 128 rows x 64 fp16 (128B rows, 16KB; attention tiles 64x64, 8KB).
// byte offset within tile: sw128(row*128 + kelem*2). cp.async is linear;
// fragment loads are ldmatrix.x4.
// =============================================================================

// ---------------- scratch (device globals; no runtime allocation) -------------
__device__ __align__(256) unsigned g_q [(size_t)Bv*Hv*Sv*32];    // fp16x2 rows, *0.125*log2e
__device__ __align__(256) unsigned g_k [(size_t)Bv*Hv*Sv*32];    // fp16x2 rows
__device__ __align__(256) unsigned g_v [(size_t)Bv*Hv*Sv*32];    // fp16x2 rows
__device__ __align__(256) unsigned g_ki[(size_t)Bv*Hv*32*2048];  // K tile images [key][hd]
__device__ __align__(256) unsigned g_vi[(size_t)Bv*Hv*32*2048];  // V^T tile images [hd][key]
__device__ __align__(256) int      g_kidx[Bv*Sv];
__device__ __align__(256) int      g_cnt[Bv];
// GEMM tile images: [tile128][chunk64k] -> 4096 words each
__device__ __align__(256) unsigned g_xa [(size_t)64*16*4096];
__device__ __align__(256) unsigned g_wi [(size_t)24*16*4096];
__device__ __align__(256) unsigned g_wo [(size_t)8*16*4096];
__device__ __align__(256) unsigned g_ci [(size_t)64*16*4096];

// ---------------- helpers -----------------------------------------------------
__device__ __forceinline__ unsigned pk2(float a, float b) {
    __half2 h = __floats2half2_rn(a, b);
    return *(unsigned*)&h;
}
__device__ __forceinline__ float ex2(float x) {
    float y;
    asm("ex2.approx.f32 %0, %1;" : "=f"(y) : "f"(x));
    return y;
}
__device__ __forceinline__ unsigned sw128(unsigned off) {
    return off ^ ((off >> 3) & 0x70);
}
__device__ __forceinline__ void mma16(float* c, const unsigned* a, const unsigned* b) {
    asm volatile(
        "mma.sync.aligned.m16n8k16.row.col.f32.f16.f16.f32 "
        "{%0,%1,%2,%3},{%4,%5,%6,%7},{%8,%9},{%0,%1,%2,%3};\n"
        : "+f"(c[0]), "+f"(c[1]), "+f"(c[2]), "+f"(c[3])
        : "r"(a[0]), "r"(a[1]), "r"(a[2]), "r"(a[3]),
          "r"(b[0]), "r"(b[1]));
}
__device__ __forceinline__ void ldsm4(unsigned* r, unsigned a) {
    asm volatile("ldmatrix.sync.aligned.m8n8.x4.shared.b16 {%0,%1,%2,%3}, [%4];"
                 : "=r"(r[0]), "=r"(r[1]), "=r"(r[2]), "=r"(r[3]) : "r"(a));
}
__device__ __forceinline__ void cpa16(unsigned sa, const void* g) {
    asm volatile("cp.async.cg.shared.global [%0], [%1], 16;\n" :: "r"(sa), "l"(g));
}
__device__ __forceinline__ void cpa_commit() {
    asm volatile("cp.async.commit_group;\n");
}
template<int N> __device__ __forceinline__ void cpa_wait() {
    asm volatile("cp.async.wait_group %0;\n" :: "n"(N));
}

// =============================================================================
// Mask scan: per batch, compacted key index list + count.
// =============================================================================
__global__ __launch_bounds__(256) void mask_scan(const int* __restrict__ mask)
{
    __shared__ int part[256];
    const int b = blockIdx.x, t = threadIdx.x;
    int loc[8], c = 0;
    #pragma unroll
    for (int j = 0; j < 8; j++) {
        loc[j] = mask[b * Sv + t * 8 + j] > 0;
        c += loc[j];
    }
    part[t] = c;
    __syncthreads();
    int pre = 0;
    for (int i = 0; i < t; i++) pre += part[i];
    int p = pre;
    #pragma unroll
    for (int j = 0; j < 8; j++)
        if (loc[j]) g_kidx[b * Sv + (p++)] = t * 8 + j;
    if (t == 255) g_cnt[b] = pre + c;
}

// =============================================================================
// Compact K/V into swizzled tile images. K: [key][hd]. V^T: [hd][key].
// grid (32, Hv, Bv), 256 threads.
// =============================================================================
__global__ __launch_bounds__(256) void compact_kv()
{
    __shared__ int sidx[64];
    __shared__ unsigned st[64][33];
    const int kt = blockIdx.x, h = blockIdx.y, b = blockIdx.z;
    const int cnt = g_cnt[b];
    if (kt * 64 >= cnt) return;
    const int bh = b * Hv + h;
    const int t = threadIdx.x;

    if (t < 64) {
        const int ci = kt * 64 + t;
        sidx[t] = (ci < cnt) ? g_kidx[b * Sv + ci] : -1;
    }
    __syncthreads();

    unsigned* kd = g_ki + ((size_t)(bh * 32 + kt)) * 2048;
    #pragma unroll
    for (int i = 0; i < 8; i++) {
        const int w = t + 256 * i;
        const int key = w >> 5, wk = w & 31;
        const int si = sidx[key];
        unsigned val = (si >= 0) ? g_k[((size_t)bh * Sv + si) * 32 + wk] : 0u;
        kd[sw128(key * 128 + wk * 4) >> 2] = val;
    }
    #pragma unroll
    for (int i = 0; i < 8; i++) {
        const int w = t + 256 * i;
        const int key = w >> 5, wk = w & 31;
        const int si = sidx[key];
        st[key][wk] = (si >= 0) ? g_v[((size_t)bh * Sv + si) * 32 + wk] : 0u;
    }
    __syncthreads();
    unsigned* vd = g_vi + ((size_t)(bh * 32 + kt)) * 2048;
    #pragma unroll
    for (int i = 0; i < 8; i++) {
        const int w = t + 256 * i;
        const int hd = w >> 5, kw = w & 31;
        unsigned sa = st[2 * kw][hd >> 1];
        unsigned sb = st[2 * kw + 1][hd >> 1];
        unsigned val = __byte_perm(sa, sb, (hd & 1) ? 0x7632 : 0x5410);
        vd[sw128(hd * 128 + kw * 4) >> 2] = val;
    }
}

// =============================================================================
// Prepass: pack X and W into swizzled fp16 tile images.
// =============================================================================
__global__ __launch_bounds__(256) void pack_x(const float* __restrict__ X)
{
    const int mtile = blockIdx.x, kb = blockIdx.y;
    const int t = threadIdx.x;
    const float* src = X + (size_t)(mtile * 128) * Dv + kb * 64;
    unsigned* dst = g_xa + ((size_t)(mtile * 16 + kb)) * 4096;
    #pragma unroll
    for (int i = 0; i < 16; i++) {
        const int w = t + 256 * i;
        const int row = w >> 5, wk = w & 31;
        float2 v = *(const float2*)(src + (size_t)row * Dv + 2 * wk);
        dst[sw128(row * 128 + wk * 4) >> 2] = pk2(v.x, v.y);
    }
}

template<int LDN>
__global__ __launch_bounds__(256) void pack_w(const float* __restrict__ W,
                                              unsigned* __restrict__ dstg)
{
    __shared__ float sb[64][129];
    const int ntile = blockIdx.x, kb = blockIdx.y;
    const int t = threadIdx.x;
    #pragma unroll
    for (int i = 0; i < 32; i++) {
        const int e = t + 256 * i;
        const int kk = e >> 7, nn = e & 127;
        sb[kk][nn] = W[(size_t)(kb * 64 + kk) * LDN + ntile * 128 + nn];
    }
    __syncthreads();
    unsigned* dst = dstg + ((size_t)(ntile * 16 + kb)) * 4096;
    #pragma unroll
    for (int i = 0; i < 16; i++) {
        const int w = t + 256 * i;
        const int nrow = w >> 5, wk = w & 31;
        dst[sw128(nrow * 128 + wk * 4) >> 2] = pk2(sb[2 * wk][nrow], sb[2 * wk + 1][nrow]);
    }
}

// =============================================================================
// QKV pair-store epilogue helper (n even; halves (n, n+1))
// =============================================================================
__device__ __forceinline__ void qkv_store2(int m, int n, float v0, float v1,
                                           const float* __restrict__ bias) {
    v0 += bias[n]; v1 += bias[n + 1];
    const int bb  = m >> 11;
    const int s   = m & 2047;
    const int sel = n >> 10;      // 0=q 1=k 2=v
    const int d   = n & 1023;
    const int h   = d >> 6;
    const int hw  = (d & 63) >> 1;
    const int bh  = bb * Hv + h;
    if (sel == 0) {
        const float qs = 0.18033688011112042f;   // 0.125*log2e
        g_q[((size_t)(bh * Sv + s)) * 32 + hw] = pk2(v0 * qs, v1 * qs);
    } else if (sel == 1) {
        g_k[((size_t)(bh * Sv + s)) * 32 + hw] = pk2(v0, v1);
    } else {
        g_v[((size_t)(bh * Sv + s)) * 32 + hw] = pk2(v0, v1);
    }
}

// =============================================================================
// fp16 GEMM on swizzled tile images. 128x128 CTA tile, BK=64, 8 warps,
// warp tile 32x64. 3-stage cp.async. ldmatrix.x4 fragments. 2 CTAs/SM.
// =============================================================================
#define GST 32768                    // stage bytes: A 16KB + B 16KB
#define GEMM_SMEM (3 * GST)

template<int NT, int EPI>
__global__ __launch_bounds__(256, 2) void gemm_tc(
    const unsigned* __restrict__ Ag,
    const unsigned* __restrict__ Bg,
    const float* __restrict__ bias,
    float* __restrict__ out)
{
    extern __shared__ unsigned char smem[];
    const unsigned sbase = (unsigned)__cvta_generic_to_shared(smem);

    const int t     = threadIdx.x;
    const int w     = t >> 5, lane = t & 31;
    const int g     = lane >> 2, tig = lane & 3;
    const int qd    = lane >> 3, r = lane & 7;
    const int ntile = blockIdx.x;
    const int mtile = blockIdx.y;
    const int m0w   = (w & 3) * 32;
    const int n0w   = (w >> 2) * 64;

    // ldmatrix per-lane address components
    const unsigned axor = r << 4;
    const unsigned aoff = (m0w + (qd & 1) * 8 + r) * 128;
    const unsigned akx  = (qd >> 1) * 16;
    const unsigned boff = (n0w + (qd >> 1) * 8 + r) * 128;
    const unsigned bkx  = (qd & 1) * 16;

    auto issue = [&](int st, int kb) {
        const char* asrc = (const char*)(Ag + ((size_t)(mtile * 16 + kb)) * 4096);
        const char* bsrc = (const char*)(Bg + ((size_t)(ntile * 16 + kb)) * 4096);
        #pragma unroll
        for (int i = 0; i < 4; i++) {
            const int e = (t + 256 * i) * 16;
            cpa16(sbase + st * GST + e, asrc + e);
            cpa16(sbase + st * GST + 16384 + e, bsrc + e);
        }
        cpa_commit();
    };

    float c[2][8][4];
    #pragma unroll
    for (int mt = 0; mt < 2; mt++)
        #pragma unroll
        for (int nt = 0; nt < 8; nt++)
            #pragma unroll
            for (int j = 0; j < 4; j++) c[mt][nt][j] = 0.f;

    issue(0, 0); issue(1, 1); issue(2, 2);

    int s = 0;
    for (int kb = 0; kb < 16; kb++) {
        cpa_wait<2>();
        __syncthreads();

        const unsigned Ab = sbase + s * GST;
        const unsigned Bb = Ab + 16384;

        #pragma unroll
        for (int ks = 0; ks < 4; ks++) {
            const unsigned ak = (ks * 32 + akx) ^ axor;
            const unsigned bk = (ks * 32 + bkx) ^ axor;
            unsigned af[2][4];
            ldsm4(af[0], Ab + aoff + ak);
            ldsm4(af[1], Ab + aoff + 2048 + ak);
            #pragma unroll
            for (int p = 0; p < 4; p++) {
                unsigned bf[4];
                ldsm4(bf, Bb + boff + p * 2048 + bk);
                mma16(c[0][2 * p],     af[0], bf);
                mma16(c[1][2 * p],     af[1], bf);
                mma16(c[0][2 * p + 1], af[0], bf + 2);
                mma16(c[1][2 * p + 1], af[1], bf + 2);
            }
        }
        __syncthreads();
        if (kb + 3 < 16) issue(s, kb + 3); else cpa_commit();
        s = (s == 2) ? 0 : s + 1;
    }

    const int row0 = mtile * 128, col0 = ntile * 128;
    if (EPI == 0) {
        #pragma unroll
        for (int mt = 0; mt < 2; mt++) {
            const int r0 = row0 + m0w + mt * 16 + g;
            const int r1 = r0 + 8;
            #pragma unroll
            for (int nt = 0; nt < 8; nt++) {
                const int n = col0 + n0w + nt * 8 + 2 * tig;
                qkv_store2(r0, n, c[mt][nt][0], c[mt][nt][1], bias);
                qkv_store2(r1, n, c[mt][nt][2], c[mt][nt][3], bias);
            }
        }
    } else {
        #pragma unroll
        for (int mt = 0; mt < 2; mt++) {
            const int r0 = row0 + m0w + mt * 16 + g;
            const int r1 = r0 + 8;
            #pragma unroll
            for (int nt = 0; nt < 8; nt++) {
                const int n = col0 + n0w + nt * 8 + 2 * tig;
                *(float2*)(out + (size_t)r0 * Dv + n) =
                    make_float2(c[mt][nt][0] + bias[n], c[mt][nt][1] + bias[n + 1]);
                *(float2*)(out + (size_t)r1 * Dv + n) =
                    make_float2(c[mt][nt][2] + bias[n], c[mt][nt][3] + bias[n + 1]);
            }
        }
    }
}

// =============================================================================
// fp16 flash attention over compacted swizzled K / V^T tile images.
// cp.async 2-stage, q-tile 128, 8 warps, log2 softmax, ldmatrix fragments.
// =============================================================================
#define AST3 16384                   // stage bytes: K 8KB + V 8KB
#define ATT_SMEM (2 * AST3)

__global__ __launch_bounds__(256, 2) void attn_tc()
{
    extern __shared__ unsigned char asmem[];
    const unsigned sbase = (unsigned)__cvta_generic_to_shared(asmem);

    const int t    = threadIdx.x;
    const int w    = t >> 5, lane = t & 31;
    const int g    = lane >> 2, tig = lane & 3;
    const int qd   = lane >> 3, r = lane & 7;
    const int qt   = blockIdx.x;
    const int h    = blockIdx.y;
    const int b    = blockIdx.z;
    const int bh   = b * Hv + h;

    const int cnt = g_cnt[b];
    const int nt_tiles = (cnt + 63) >> 6;

    // B-role ldmatrix address components (same for K and V^T tiles)
    const unsigned xorv = r << 4;
    const unsigned broff = ((qd >> 1) * 8 + r) * 128;
    const unsigned bkx   = (qd & 1) * 16;

    auto issue = [&](int st, int kt) {
        const char* ksrc = (const char*)(g_ki + ((size_t)(bh * 32 + kt)) * 2048);
        const char* vsrc = (const char*)(g_vi + ((size_t)(bh * 32 + kt)) * 2048);
        #pragma unroll
        for (int i = 0; i < 2; i++) {
            const int e = (t + 256 * i) * 16;
            cpa16(sbase + st * AST3 + e, ksrc + e);
            cpa16(sbase + st * AST3 + 8192 + e, vsrc + e);
        }
        cpa_commit();
    };

    // ---- preload Q fragments ----
    unsigned q[4][4];
    const unsigned* qp = g_q + ((size_t)bh * Sv + qt * 128 + w * 16) * 32;
    #pragma unroll
    for (int ks = 0; ks < 4; ks++) {
        q[ks][0] = qp[g * 32       + ks * 8 + tig];
        q[ks][1] = qp[(g + 8) * 32 + ks * 8 + tig];
        q[ks][2] = qp[g * 32       + ks * 8 + tig + 4];
        q[ks][3] = qp[(g + 8) * 32 + ks * 8 + tig + 4];
    }

    float o[8][4];
    #pragma unroll
    for (int nt = 0; nt < 8; nt++)
        #pragma unroll
        for (int j = 0; j < 4; j++) o[nt][j] = 0.f;

    float m0r = -1e30f, m1r = -1e30f, l0 = 0.f, l1 = 0.f;

    issue(0, 0);
    if (nt_tiles > 1) issue(1, 1); else cpa_commit();

    for (int kt = 0; kt < nt_tiles; kt++) {
        cpa_wait<1>();
        __syncthreads();

        const unsigned Kb = sbase + (kt & 1) * AST3;
        const unsigned Vb = Kb + 8192;

        // ---- S = Q K^T (log2 domain) ----
        float s[8][4];
        #pragma unroll
        for (int nt = 0; nt < 8; nt++)
            #pragma unroll
            for (int j = 0; j < 4; j++) s[nt][j] = 0.f;

        #pragma unroll
        for (int ks = 0; ks < 4; ks++) {
            const unsigned bk = (ks * 32 + bkx) ^ xorv;
            #pragma unroll
            for (int p = 0; p < 4; p++) {
                unsigned bf[4];
                ldsm4(bf, Kb + broff + p * 2048 + bk);
                mma16(s[2 * p],     q[ks], bf);
                mma16(s[2 * p + 1], q[ks], bf + 2);
            }
        }

        // ---- tail predicate (last tile only) ----
        const int limit = cnt - kt * 64;
        if (limit < 64) {
            #pragma unroll
            for (int nt = 0; nt < 8; nt++) {
                const int cc = nt * 8 + 2 * tig;
                if (cc >= limit)     { s[nt][0] = -1e30f; s[nt][2] = -1e30f; }
                if (cc + 1 >= limit) { s[nt][1] = -1e30f; s[nt][3] = -1e30f; }
            }
        }

        // ---- row max ----
        float mx0 = -1e30f, mx1 = -1e30f;
        #pragma unroll
        for (int nt = 0; nt < 8; nt++) {
            mx0 = fmaxf(mx0, fmaxf(s[nt][0], s[nt][1]));
            mx1 = fmaxf(mx1, fmaxf(s[nt][2], s[nt][3]));
        }
        mx0 = fmaxf(mx0, __shfl_xor_sync(0xffffffffu, mx0, 1));
        mx0 = fmaxf(mx0, __shfl_xor_sync(0xffffffffu, mx0, 2));
        mx1 = fmaxf(mx1, __shfl_xor_sync(0xffffffffu, mx1, 1));
        mx1 = fmaxf(mx1, __shfl_xor_sync(0xffffffffu, mx1, 2));

        const float mn0 = fmaxf(m0r, mx0);
        const float mn1 = fmaxf(m1r, mx1);
        const float cr0 = ex2(m0r - mn0);
        const float cr1 = ex2(m1r - mn1);
        m0r = mn0; m1r = mn1;

        // ---- exp2 + row sums ----
        float a0 = 0.f, a1 = 0.f;
        #pragma unroll
        for (int nt = 0; nt < 8; nt++) {
            s[nt][0] = ex2(s[nt][0] - mn0);
            s[nt][1] = ex2(s[nt][1] - mn0);
            s[nt][2] = ex2(s[nt][2] - mn1);
            s[nt][3] = ex2(s[nt][3] - mn1);
            a0 += s[nt][0] + s[nt][1];
            a1 += s[nt][2] + s[nt][3];
        }
        a0 += __shfl_xor_sync(0xffffffffu, a0, 1);
        a0 += __shfl_xor_sync(0xffffffffu, a0, 2);
        a1 += __shfl_xor_sync(0xffffffffu, a1, 1);
        a1 += __shfl_xor_sync(0xffffffffu, a1, 2);
        l0 = l0 * cr0 + a0;
        l1 = l1 * cr1 + a1;

        // ---- rescale O ----
        #pragma unroll
        for (int nt = 0; nt < 8; nt++) {
            o[nt][0] *= cr0; o[nt][1] *= cr0;
            o[nt][2] *= cr1; o[nt][3] *= cr1;
        }

        // ---- O += P V  (P packs straight into A-frags; B via ldmatrix) ----
        #pragma unroll
        for (int ks = 0; ks < 4; ks++) {
            unsigned a[4];
            a[0] = pk2(s[2*ks][0],     s[2*ks][1]);
            a[1] = pk2(s[2*ks][2],     s[2*ks][3]);
            a[2] = pk2(s[2*ks + 1][0], s[2*ks + 1][1]);
            a[3] = pk2(s[2*ks + 1][2], s[2*ks + 1][3]);
            const unsigned bk = (ks * 32 + bkx) ^ xorv;
            #pragma unroll
            for (int p = 0; p < 4; p++) {
                unsigned bf[4];
                ldsm4(bf, Vb + broff + p * 2048 + bk);
                mma16(o[2 * p],     a, bf);
                mma16(o[2 * p + 1], a, bf + 2);
            }
        }

        __syncthreads();
        if (kt + 2 < nt_tiles) issue(kt & 1, kt + 2); else cpa_commit();
    }

    // ---- normalize and write ctx tile image (swizzled) ----
    const float inv0 = 1.0f / l0;
    const float inv1 = 1.0f / l1;
    const int mtile = b * 16 + qt;
    const int tr = w * 16 + g;
    unsigned* cbase = g_ci + ((size_t)(mtile * 16 + h)) * 4096;
    #pragma unroll
    for (int nt = 0; nt < 8; nt++) {
        const int kin = nt * 8 + 2 * tig;
        cbase[sw128(tr * 128 + kin * 2) >> 2]       = pk2(o[nt][0] * inv0, o[nt][1] * inv0);
        cbase[sw128((tr + 8) * 128 + kin * 2) >> 2] = pk2(o[nt][2] * inv1, o[nt][3] * inv1);
    }
}

// =============================================================================
extern "C" void kernel_launch(void* const* d_in, const int* in_sizes, int n_in,
                              void* d_out, int out_size)
{
    const float* x     = (const float*)d_in[0];
    const float* w_in  = (const float*)d_in[1];
    const float* b_in  = (const float*)d_in[2];
    const float* w_out = (const float*)d_in[3];
    const float* b_out = (const float*)d_in[4];
    const int*   mask  = (const int*)d_in[5];
    float* out = (float*)d_out;

    cudaFuncSetAttribute(gemm_tc<24, 0>, cudaFuncAttributeMaxDynamicSharedMemorySize, GEMM_SMEM);
    cudaFuncSetAttribute(gemm_tc<8, 1>,  cudaFuncAttributeMaxDynamicSharedMemorySize, GEMM_SMEM);
    cudaFuncSetAttribute(attn_tc,        cudaFuncAttributeMaxDynamicSharedMemorySize, ATT_SMEM);

    unsigned *xa, *wi, *wo, *ci;
    cudaGetSymbolAddress((void**)&xa, g_xa);
    cudaGetSymbolAddress((void**)&wi, g_wi);
    cudaGetSymbolAddress((void**)&wo, g_wo);
    cudaGetSymbolAddress((void**)&ci, g_ci);

    mask_scan<<<Bv, 256>>>(mask);
    pack_x<<<dim3(64, 16), 256>>>(x);
    pack_w<N3v><<<dim3(24, 16), 256>>>(w_in, wi);
    pack_w<Dv><<<dim3(8, 16), 256>>>(w_out, wo);
    gemm_tc<24, 0><<<dim3(24, 64), 256, GEMM_SMEM>>>(xa, wi, b_in, nullptr);
    compact_kv<<<dim3(32, Hv, Bv), 256>>>();
    attn_tc<<<dim3(Sv / 128, Hv, Bv), 256, ATT_SMEM>>>();
    gemm_tc<8, 1><<<dim3(8, 64), 256, GEMM_SMEM>>>(ci, wo, b_out, out);
}